// round 1
// baseline (speedup 1.0000x reference)
#include <cuda_runtime.h>
#include <math.h>

// Problem dims (fixed for this problem instance)
#define Bb 2
#define Ss 2048
#define Cc 2048
#define HD 64
#define Hh 32              // Cc / HD
#define BSs (Bb * Ss)      // 4096
#define C3 (3 * Cc)        // 6144

// ---------------- scratch (no allocations allowed) ----------------
__device__ float g_qkv[(size_t)BSs * C3];        // [B,S,3C]   ~100.7 MB
__device__ float g_q[(size_t)Bb * Hh * Ss * HD]; // [B,H,S,hd] ~33.6 MB (pre-scaled by 1/8)
__device__ float g_k[(size_t)Bb * Hh * Ss * HD];
__device__ float g_v[(size_t)Bb * Hh * Ss * HD];
__device__ float g_attn[(size_t)BSs * Cc];       // [B,S,C]

// =====================================================================
// GEMM (NT): Cmat[m,n] = sum_k A[m,k] * W[n,k]
// A: [M,K] row-major, W: [N,K] row-major. 128x128 tile, BK=16, 8x8/thread.
// =====================================================================
__global__ __launch_bounds__(256) void gemm_nt_kernel(
    const float* __restrict__ A, const float* __restrict__ W,
    float* __restrict__ Cmat, int M, int N, int K)
{
    __shared__ float As[16][128];
    __shared__ float Bs[16][128];

    const int tid = threadIdx.x;
    const int m0 = blockIdx.y * 128;
    const int n0 = blockIdx.x * 128;
    const int tx = tid & 15;   // 0..15 -> n sub-block
    const int ty = tid >> 4;   // 0..15 -> m sub-block

    const int lrow = tid >> 2;       // 0..63
    const int lk4  = (tid & 3) << 2; // 0,4,8,12

    float acc[8][8];
#pragma unroll
    for (int i = 0; i < 8; i++)
#pragma unroll
        for (int j = 0; j < 8; j++) acc[i][j] = 0.f;

    for (int k0 = 0; k0 < K; k0 += 16) {
#pragma unroll
        for (int t = 0; t < 2; t++) {
            int row = lrow + t * 64;
            float4 a = *(const float4*)(A + (size_t)(m0 + row) * K + k0 + lk4);
            As[lk4 + 0][row] = a.x; As[lk4 + 1][row] = a.y;
            As[lk4 + 2][row] = a.z; As[lk4 + 3][row] = a.w;
            float4 b = *(const float4*)(W + (size_t)(n0 + row) * K + k0 + lk4);
            Bs[lk4 + 0][row] = b.x; Bs[lk4 + 1][row] = b.y;
            Bs[lk4 + 2][row] = b.z; Bs[lk4 + 3][row] = b.w;
        }
        __syncthreads();

#pragma unroll
        for (int kk = 0; kk < 16; kk++) {
            float ar[8], br[8];
#pragma unroll
            for (int i = 0; i < 2; i++) {
                float4 t4 = *(const float4*)&As[kk][ty * 8 + i * 4];
                ar[i * 4 + 0] = t4.x; ar[i * 4 + 1] = t4.y;
                ar[i * 4 + 2] = t4.z; ar[i * 4 + 3] = t4.w;
                float4 u4 = *(const float4*)&Bs[kk][tx * 8 + i * 4];
                br[i * 4 + 0] = u4.x; br[i * 4 + 1] = u4.y;
                br[i * 4 + 2] = u4.z; br[i * 4 + 3] = u4.w;
            }
#pragma unroll
            for (int i = 0; i < 8; i++)
#pragma unroll
                for (int j = 0; j < 8; j++)
                    acc[i][j] += ar[i] * br[j];
        }
        __syncthreads();
    }

#pragma unroll
    for (int i = 0; i < 8; i++) {
        float* crow = Cmat + (size_t)(m0 + ty * 8 + i) * N + n0 + tx * 8;
        *(float4*)(crow + 0) = make_float4(acc[i][0], acc[i][1], acc[i][2], acc[i][3]);
        *(float4*)(crow + 4) = make_float4(acc[i][4], acc[i][5], acc[i][6], acc[i][7]);
    }
}

// =====================================================================
// Fused LayerNorm (per-head, eps=1e-5, biased var) + rotary + V copy.
// One warp per (b,s,h). Q is pre-scaled by 1/sqrt(hd)=0.125.
// Output layout: [B,H,S,hd] (head-major for attention).
// =====================================================================
__global__ __launch_bounds__(256) void lnrope_kernel(
    const float* __restrict__ qkv, const float* __restrict__ rope,
    const float* __restrict__ qg, const float* __restrict__ qb,
    const float* __restrict__ kg, const float* __restrict__ kb,
    float* __restrict__ Qo, float* __restrict__ Ko, float* __restrict__ Vo)
{
    int gw   = (blockIdx.x * blockDim.x + threadIdx.x) >> 5;
    int lane = threadIdx.x & 31;
    if (gw >= Bb * Ss * Hh) return;
    int h = gw % Hh;
    int s = (gw / Hh) % Ss;
    int b = gw / (Hh * Ss);

    const float* base = qkv + ((size_t)(b * Ss + s)) * C3 + h * (3 * HD);
    float4 r4 = *(const float4*)(rope + (size_t)s * 128 + lane * 4);
    size_t obase = (((size_t)(b * Hh + h)) * Ss + s) * HD + 2 * lane;

    float gq0 = qg[2 * lane], gq1 = qg[2 * lane + 1];
    float bq0 = qb[2 * lane], bq1 = qb[2 * lane + 1];
    float gk0 = kg[2 * lane], gk1 = kg[2 * lane + 1];
    float bk0 = kb[2 * lane], bk1 = kb[2 * lane + 1];

    // ---- Q ----
    {
        float2 x2 = *(const float2*)(base + 2 * lane);
        float sum = x2.x + x2.y;
#pragma unroll
        for (int o = 16; o; o >>= 1) sum += __shfl_xor_sync(0xffffffffu, sum, o);
        float mean = sum * (1.f / 64.f);
        float d0 = x2.x - mean, d1 = x2.y - mean;
        float vs = d0 * d0 + d1 * d1;
#pragma unroll
        for (int o = 16; o; o >>= 1) vs += __shfl_xor_sync(0xffffffffu, vs, o);
        float inv = rsqrtf(vs * (1.f / 64.f) + 1e-5f);
        float n0 = d0 * inv * gq0 + bq0;
        float n1 = d1 * inv * gq1 + bq1;
        float o0 = r4.x * n0 + r4.y * n1;
        float o1 = r4.z * n0 + r4.w * n1;
        *(float2*)(Qo + obase) = make_float2(o0 * 0.125f, o1 * 0.125f);
    }
    // ---- K ----
    {
        float2 x2 = *(const float2*)(base + HD + 2 * lane);
        float sum = x2.x + x2.y;
#pragma unroll
        for (int o = 16; o; o >>= 1) sum += __shfl_xor_sync(0xffffffffu, sum, o);
        float mean = sum * (1.f / 64.f);
        float d0 = x2.x - mean, d1 = x2.y - mean;
        float vs = d0 * d0 + d1 * d1;
#pragma unroll
        for (int o = 16; o; o >>= 1) vs += __shfl_xor_sync(0xffffffffu, vs, o);
        float inv = rsqrtf(vs * (1.f / 64.f) + 1e-5f);
        float n0 = d0 * inv * gk0 + bk0;
        float n1 = d1 * inv * gk1 + bk1;
        float o0 = r4.x * n0 + r4.y * n1;
        float o1 = r4.z * n0 + r4.w * n1;
        *(float2*)(Ko + obase) = make_float2(o0, o1);
    }
    // ---- V copy ----
    {
        float2 x2 = *(const float2*)(base + 2 * HD + 2 * lane);
        *(float2*)(Vo + obase) = x2;
    }
}

// =====================================================================
// Flash-style fp32 attention. Grid: (S/64, B*H). Block: 256 (8 warps).
// Warp w owns score/output rows w*8 .. w*8+7; lane owns cols 2l,2l+1.
// Online softmax across k-tiles of 64. Q pre-scaled (scores = q.k).
// Output written as [B,S,H*hd].
// =====================================================================
#define QK_STRIDE 65
#define V_STRIDE  66
#define ATTN_SMEM ((3 * 64 * QK_STRIDE + 64 * V_STRIDE) * 4)

__global__ __launch_bounds__(256) void attn_kernel(
    const float* __restrict__ Qg, const float* __restrict__ Kg,
    const float* __restrict__ Vg, float* __restrict__ Og)
{
    extern __shared__ float sm[];
    float* Qs = sm;                        // 64 x 65
    float* Ks = Qs + 64 * QK_STRIDE;       // 64 x 65
    float* Ps = Ks + 64 * QK_STRIDE;       // 64 x 65
    float* Vs = Ps + 64 * QK_STRIDE;       // 64 x 66

    const int bh = blockIdx.y;
    const int b = bh >> 5;        // / Hh
    const int h = bh & (Hh - 1);
    const int qt = blockIdx.x;

    const float* Q = Qg + ((size_t)bh * Ss + qt * 64) * HD;
    const float* K = Kg + (size_t)bh * Ss * HD;
    const float* V = Vg + (size_t)bh * Ss * HD;

    const int tid = threadIdx.x;
    const int warp = tid >> 5, lane = tid & 31;

    // load Q tile
#pragma unroll
    for (int t = 0; t < 4; t++) {
        int lin = tid + t * 256;   // float4 index, 0..1023
        int row = lin >> 4;
        int c4 = (lin & 15) << 2;
        float4 v = *(const float4*)(Q + row * HD + c4);
        Qs[row * QK_STRIDE + c4 + 0] = v.x;
        Qs[row * QK_STRIDE + c4 + 1] = v.y;
        Qs[row * QK_STRIDE + c4 + 2] = v.z;
        Qs[row * QK_STRIDE + c4 + 3] = v.w;
    }
    __syncthreads();

    float m[8], l[8], o0[8], o1[8];
#pragma unroll
    for (int r = 0; r < 8; r++) { m[r] = -1e30f; l[r] = 0.f; o0[r] = 0.f; o1[r] = 0.f; }

    for (int kt = 0; kt < Ss / 64; kt++) {
        const float* Kt = K + kt * 64 * HD;
        const float* Vt = V + kt * 64 * HD;
#pragma unroll
        for (int t = 0; t < 4; t++) {
            int lin = tid + t * 256;
            int row = lin >> 4;
            int c4 = (lin & 15) << 2;
            float4 kv = *(const float4*)(Kt + row * HD + c4);
            Ks[row * QK_STRIDE + c4 + 0] = kv.x;
            Ks[row * QK_STRIDE + c4 + 1] = kv.y;
            Ks[row * QK_STRIDE + c4 + 2] = kv.z;
            Ks[row * QK_STRIDE + c4 + 3] = kv.w;
            float4 vv = *(const float4*)(Vt + row * HD + c4);
            Vs[row * V_STRIDE + c4 + 0] = vv.x;
            Vs[row * V_STRIDE + c4 + 1] = vv.y;
            Vs[row * V_STRIDE + c4 + 2] = vv.z;
            Vs[row * V_STRIDE + c4 + 3] = vv.w;
        }
        __syncthreads();

        // scores: s[r][2l], s[r][2l+1]
        float s0[8], s1[8];
#pragma unroll
        for (int r = 0; r < 8; r++) { s0[r] = 0.f; s1[r] = 0.f; }
        const float* krow0 = Ks + (2 * lane) * QK_STRIDE;
        const float* krow1 = krow0 + QK_STRIDE;
        const float* qbase = Qs + warp * 8 * QK_STRIDE;
#pragma unroll 4
        for (int d = 0; d < 64; d++) {
            float k0 = krow0[d], k1 = krow1[d];
#pragma unroll
            for (int r = 0; r < 8; r++) {
                float q = qbase[r * QK_STRIDE + d];
                s0[r] += q * k0;
                s1[r] += q * k1;
            }
        }

        float alpha[8];
#pragma unroll
        for (int r = 0; r < 8; r++) {
            float mx = fmaxf(s0[r], s1[r]);
#pragma unroll
            for (int o2 = 16; o2; o2 >>= 1)
                mx = fmaxf(mx, __shfl_xor_sync(0xffffffffu, mx, o2));
            float mnew = fmaxf(m[r], mx);
            float p0 = __expf(s0[r] - mnew);
            float p1 = __expf(s1[r] - mnew);
            float rs = p0 + p1;
#pragma unroll
            for (int o2 = 16; o2; o2 >>= 1)
                rs += __shfl_xor_sync(0xffffffffu, rs, o2);
            alpha[r] = __expf(m[r] - mnew);
            l[r] = l[r] * alpha[r] + rs;
            m[r] = mnew;
            Ps[(warp * 8 + r) * QK_STRIDE + 2 * lane]     = p0;
            Ps[(warp * 8 + r) * QK_STRIDE + 2 * lane + 1] = p1;
        }
        __syncwarp();

        // O += P @ V
#pragma unroll
        for (int r = 0; r < 8; r++) {
            float a0 = o0[r] * alpha[r];
            float a1 = o1[r] * alpha[r];
            const float* prow = Ps + (warp * 8 + r) * QK_STRIDE;
#pragma unroll 4
            for (int c = 0; c < 64; c++) {
                float p = prow[c];
                float2 v = *(const float2*)(Vs + c * V_STRIDE + 2 * lane);
                a0 += p * v.x;
                a1 += p * v.y;
            }
            o0[r] = a0; o1[r] = a1;
        }
        __syncthreads();
    }

#pragma unroll
    for (int r = 0; r < 8; r++) {
        float inv = 1.f / l[r];
        int srow = qt * 64 + warp * 8 + r;
        *(float2*)(Og + ((size_t)(b * Ss + srow)) * Cc + h * HD + 2 * lane) =
            make_float2(o0[r] * inv, o1[r] * inv);
    }
}

// =====================================================================
extern "C" void kernel_launch(void* const* d_in, const int* in_sizes, int n_in,
                              void* d_out, int out_size)
{
    const float* x    = (const float*)d_in[0];
    const float* rope = (const float*)d_in[1];
    const float* wqkv = (const float*)d_in[2];
    const float* wout = (const float*)d_in[3];
    const float* qg   = (const float*)d_in[4];
    const float* qb   = (const float*)d_in[5];
    const float* kg   = (const float*)d_in[6];
    const float* kb   = (const float*)d_in[7];
    float* out = (float*)d_out;

    float *qkv, *q, *k, *v, *attn;
    cudaGetSymbolAddress((void**)&qkv,  g_qkv);
    cudaGetSymbolAddress((void**)&q,    g_q);
    cudaGetSymbolAddress((void**)&k,    g_k);
    cudaGetSymbolAddress((void**)&v,    g_v);
    cudaGetSymbolAddress((void**)&attn, g_attn);

    // 1) QKV projection: [4096,2048] x [6144,2048]^T -> [4096,6144]
    gemm_nt_kernel<<<dim3(C3 / 128, BSs / 128), 256>>>(x, wqkv, qkv, BSs, C3, Cc);

    // 2) per-head LN + rotary + V copy -> [B,H,S,hd]
    lnrope_kernel<<<(Bb * Ss * Hh * 32) / 256, 256>>>(qkv, rope, qg, qb, kg, kb, q, k, v);

    // 3) attention
    cudaFuncSetAttribute(attn_kernel, cudaFuncAttributeMaxDynamicSharedMemorySize, ATTN_SMEM);
    attn_kernel<<<dim3(Ss / 64, Bb * Hh), 256, ATTN_SMEM>>>(q, k, v, attn);

    // 4) output projection: [4096,2048] x [2048,2048]^T -> [4096,2048]
    gemm_nt_kernel<<<dim3(Cc / 128, BSs / 128), 256>>>(attn, wout, out, BSs, Cc, Cc);
}

// round 2
// speedup vs baseline: 1.4359x; 1.4359x over previous
#include <cuda_runtime.h>
#include <math.h>

// Problem dims (fixed for this problem instance)
#define Bb 2
#define Ss 2048
#define Cc 2048
#define HD 64
#define Hh 32              // Cc / HD
#define BSs (Bb * Ss)      // 4096
#define C3 (3 * Cc)        // 6144

// ---------------- scratch (no allocations allowed) ----------------
__device__ float g_qkv[(size_t)BSs * C3];        // [B,S,3C]
__device__ float g_q[(size_t)Bb * Hh * Ss * HD]; // [B,H,S,hd] (Q pre-scaled by 1/8)
__device__ float g_k[(size_t)Bb * Hh * Ss * HD];
__device__ float g_v[(size_t)Bb * Hh * Ss * HD];
__device__ float g_attn[(size_t)BSs * Cc];       // [B,S,C]

// =====================================================================
// TF32 tensor-core GEMM (NT): Cmat[m,n] = sum_k A[m,k] * W[n,k]
// A: [M,K] row-major, W: [N,K] row-major.
// 128x128 CTA tile, BK=32, 256 threads = 8 warps, warp tile 64x32.
// mma.sync.aligned.m16n8k8.row.col.f32.tf32.tf32.f32
// Smem stride 36 words -> conflict-free fragment loads (bank = 4*gid+tig).
// =====================================================================
__device__ __forceinline__ unsigned f2tf(float f) {
    unsigned u;
    asm("cvt.rna.tf32.f32 %0, %1;" : "=r"(u) : "f"(f));
    return u;
}

__device__ __forceinline__ void mma_tf32(float c[4], const unsigned a[4], const unsigned b[2]) {
    asm volatile(
        "mma.sync.aligned.m16n8k8.row.col.f32.tf32.tf32.f32 "
        "{%0,%1,%2,%3}, {%4,%5,%6,%7}, {%8,%9}, {%0,%1,%2,%3};\n"
        : "+f"(c[0]), "+f"(c[1]), "+f"(c[2]), "+f"(c[3])
        : "r"(a[0]), "r"(a[1]), "r"(a[2]), "r"(a[3]), "r"(b[0]), "r"(b[1]));
}

#define GS 36   // smem row stride in words (conflict-free for frag loads)

__global__ __launch_bounds__(256) void gemm_tf32_kernel(
    const float* __restrict__ A, const float* __restrict__ W,
    float* __restrict__ Cmat, int M, int N, int K)
{
    __shared__ unsigned As[128 * GS];
    __shared__ unsigned Bs[128 * GS];

    const int tid  = threadIdx.x;
    const int m0   = blockIdx.y * 128;
    const int n0   = blockIdx.x * 128;
    const int warp = tid >> 5;
    const int lane = tid & 31;
    const int gid  = lane >> 2;   // 0..7
    const int tig  = lane & 3;    // 0..3
    const int wm   = (warp & 1) * 64;   // warp M offset within CTA tile
    const int wn   = (warp >> 1) * 32;  // warp N offset

    // global staging layout: each thread loads 4 rows (stride 32) x 4 floats
    const int lr = tid >> 3;          // 0..31
    const int lk = (tid & 7) << 2;    // 0,4,...,28

    float c[4][4][4];
#pragma unroll
    for (int mt = 0; mt < 4; mt++)
#pragma unroll
        for (int nt = 0; nt < 4; nt++)
#pragma unroll
            for (int i = 0; i < 4; i++) c[mt][nt][i] = 0.f;

    const float* Ag = A + (size_t)(m0 + lr) * K + lk;
    const float* Bg = W + (size_t)(n0 + lr) * K + lk;

    float4 ra[4], rb[4];
#pragma unroll
    for (int p = 0; p < 4; p++) {
        ra[p] = *(const float4*)(Ag + (size_t)(p * 32) * K);
        rb[p] = *(const float4*)(Bg + (size_t)(p * 32) * K);
    }
    // store tile 0 (with tf32 RNA rounding)
#pragma unroll
    for (int p = 0; p < 4; p++) {
        uint4 ua = make_uint4(f2tf(ra[p].x), f2tf(ra[p].y), f2tf(ra[p].z), f2tf(ra[p].w));
        *(uint4*)&As[(lr + p * 32) * GS + lk] = ua;
        uint4 ub = make_uint4(f2tf(rb[p].x), f2tf(rb[p].y), f2tf(rb[p].z), f2tf(rb[p].w));
        *(uint4*)&Bs[(lr + p * 32) * GS + lk] = ub;
    }

    const int ntiles = K >> 5;
    for (int t = 0; t < ntiles; t++) {
        if (t + 1 < ntiles) {
            const float* Ap = Ag + (size_t)(t + 1) * 32;
            const float* Bp = Bg + (size_t)(t + 1) * 32;
#pragma unroll
            for (int p = 0; p < 4; p++) {
                ra[p] = *(const float4*)(Ap + (size_t)(p * 32) * K);
                rb[p] = *(const float4*)(Bp + (size_t)(p * 32) * K);
            }
        }
        __syncthreads();

#pragma unroll
        for (int kk = 0; kk < 32; kk += 8) {
            unsigned af[4][4], bf[4][2];
#pragma unroll
            for (int mt = 0; mt < 4; mt++) {
                int row = wm + mt * 16;
                af[mt][0] = As[(row + gid) * GS + kk + tig];
                af[mt][1] = As[(row + gid + 8) * GS + kk + tig];
                af[mt][2] = As[(row + gid) * GS + kk + tig + 4];
                af[mt][3] = As[(row + gid + 8) * GS + kk + tig + 4];
            }
#pragma unroll
            for (int nt = 0; nt < 4; nt++) {
                int col = wn + nt * 8;
                bf[nt][0] = Bs[(col + gid) * GS + kk + tig];
                bf[nt][1] = Bs[(col + gid) * GS + kk + tig + 4];
            }
#pragma unroll
            for (int mt = 0; mt < 4; mt++)
#pragma unroll
                for (int nt = 0; nt < 4; nt++)
                    mma_tf32(c[mt][nt], af[mt], bf[nt]);
        }
        __syncthreads();

        if (t + 1 < ntiles) {
#pragma unroll
            for (int p = 0; p < 4; p++) {
                uint4 ua = make_uint4(f2tf(ra[p].x), f2tf(ra[p].y), f2tf(ra[p].z), f2tf(ra[p].w));
                *(uint4*)&As[(lr + p * 32) * GS + lk] = ua;
                uint4 ub = make_uint4(f2tf(rb[p].x), f2tf(rb[p].y), f2tf(rb[p].z), f2tf(rb[p].w));
                *(uint4*)&Bs[(lr + p * 32) * GS + lk] = ub;
            }
        }
    }

    // epilogue
#pragma unroll
    for (int mt = 0; mt < 4; mt++) {
        int row0 = m0 + wm + mt * 16 + gid;
        int row1 = row0 + 8;
#pragma unroll
        for (int nt = 0; nt < 4; nt++) {
            int col = n0 + wn + nt * 8 + tig * 2;
            *(float2*)(Cmat + (size_t)row0 * N + col) = make_float2(c[mt][nt][0], c[mt][nt][1]);
            *(float2*)(Cmat + (size_t)row1 * N + col) = make_float2(c[mt][nt][2], c[mt][nt][3]);
        }
    }
}

// =====================================================================
// Fused LayerNorm (per-head, eps=1e-5, biased var) + rotary + V copy.
// One warp per (b,s,h). Q is pre-scaled by 1/sqrt(hd)=0.125.
// Output layout: [B,H,S,hd] (head-major for attention).
// =====================================================================
__global__ __launch_bounds__(256) void lnrope_kernel(
    const float* __restrict__ qkv, const float* __restrict__ rope,
    const float* __restrict__ qg, const float* __restrict__ qb,
    const float* __restrict__ kg, const float* __restrict__ kb,
    float* __restrict__ Qo, float* __restrict__ Ko, float* __restrict__ Vo)
{
    int gw   = (blockIdx.x * blockDim.x + threadIdx.x) >> 5;
    int lane = threadIdx.x & 31;
    if (gw >= Bb * Ss * Hh) return;
    int h = gw % Hh;
    int s = (gw / Hh) % Ss;
    int b = gw / (Hh * Ss);

    const float* base = qkv + ((size_t)(b * Ss + s)) * C3 + h * (3 * HD);
    float4 r4 = *(const float4*)(rope + (size_t)s * 128 + lane * 4);
    size_t obase = (((size_t)(b * Hh + h)) * Ss + s) * HD + 2 * lane;

    float gq0 = qg[2 * lane], gq1 = qg[2 * lane + 1];
    float bq0 = qb[2 * lane], bq1 = qb[2 * lane + 1];
    float gk0 = kg[2 * lane], gk1 = kg[2 * lane + 1];
    float bk0 = kb[2 * lane], bk1 = kb[2 * lane + 1];

    // ---- Q ----
    {
        float2 x2 = *(const float2*)(base + 2 * lane);
        float sum = x2.x + x2.y;
#pragma unroll
        for (int o = 16; o; o >>= 1) sum += __shfl_xor_sync(0xffffffffu, sum, o);
        float mean = sum * (1.f / 64.f);
        float d0 = x2.x - mean, d1 = x2.y - mean;
        float vs = d0 * d0 + d1 * d1;
#pragma unroll
        for (int o = 16; o; o >>= 1) vs += __shfl_xor_sync(0xffffffffu, vs, o);
        float inv = rsqrtf(vs * (1.f / 64.f) + 1e-5f);
        float n0 = d0 * inv * gq0 + bq0;
        float n1 = d1 * inv * gq1 + bq1;
        float o0 = r4.x * n0 + r4.y * n1;
        float o1 = r4.z * n0 + r4.w * n1;
        *(float2*)(Qo + obase) = make_float2(o0 * 0.125f, o1 * 0.125f);
    }
    // ---- K ----
    {
        float2 x2 = *(const float2*)(base + HD + 2 * lane);
        float sum = x2.x + x2.y;
#pragma unroll
        for (int o = 16; o; o >>= 1) sum += __shfl_xor_sync(0xffffffffu, sum, o);
        float mean = sum * (1.f / 64.f);
        float d0 = x2.x - mean, d1 = x2.y - mean;
        float vs = d0 * d0 + d1 * d1;
#pragma unroll
        for (int o = 16; o; o >>= 1) vs += __shfl_xor_sync(0xffffffffu, vs, o);
        float inv = rsqrtf(vs * (1.f / 64.f) + 1e-5f);
        float n0 = d0 * inv * gk0 + bk0;
        float n1 = d1 * inv * gk1 + bk1;
        float o0 = r4.x * n0 + r4.y * n1;
        float o1 = r4.z * n0 + r4.w * n1;
        *(float2*)(Ko + obase) = make_float2(o0, o1);
    }
    // ---- V copy ----
    {
        float2 x2 = *(const float2*)(base + 2 * HD + 2 * lane);
        *(float2*)(Vo + obase) = x2;
    }
}

// =====================================================================
// Flash-style fp32 attention. Grid: (S/64, B*H). Block: 256 (8 warps).
// Warp w owns score/output rows w*8 .. w*8+7; lane owns cols 2l,2l+1.
// Online softmax across k-tiles of 64. Q pre-scaled (scores = q.k).
// Output written as [B,S,H*hd].
// =====================================================================
#define QK_STRIDE 65
#define V_STRIDE  66
#define ATTN_SMEM ((3 * 64 * QK_STRIDE + 64 * V_STRIDE) * 4)

__global__ __launch_bounds__(256) void attn_kernel(
    const float* __restrict__ Qg, const float* __restrict__ Kg,
    const float* __restrict__ Vg, float* __restrict__ Og)
{
    extern __shared__ float sm[];
    float* Qs = sm;                        // 64 x 65
    float* Ks = Qs + 64 * QK_STRIDE;       // 64 x 65
    float* Ps = Ks + 64 * QK_STRIDE;       // 64 x 65
    float* Vs = Ps + 64 * QK_STRIDE;       // 64 x 66

    const int bh = blockIdx.y;
    const int b = bh >> 5;        // / Hh
    const int h = bh & (Hh - 1);
    const int qt = blockIdx.x;

    const float* Q = Qg + ((size_t)bh * Ss + qt * 64) * HD;
    const float* K = Kg + (size_t)bh * Ss * HD;
    const float* V = Vg + (size_t)bh * Ss * HD;

    const int tid = threadIdx.x;
    const int warp = tid >> 5, lane = tid & 31;

    // load Q tile
#pragma unroll
    for (int t = 0; t < 4; t++) {
        int lin = tid + t * 256;   // float4 index, 0..1023
        int row = lin >> 4;
        int c4 = (lin & 15) << 2;
        float4 v = *(const float4*)(Q + row * HD + c4);
        Qs[row * QK_STRIDE + c4 + 0] = v.x;
        Qs[row * QK_STRIDE + c4 + 1] = v.y;
        Qs[row * QK_STRIDE + c4 + 2] = v.z;
        Qs[row * QK_STRIDE + c4 + 3] = v.w;
    }
    __syncthreads();

    float m[8], l[8], o0[8], o1[8];
#pragma unroll
    for (int r = 0; r < 8; r++) { m[r] = -1e30f; l[r] = 0.f; o0[r] = 0.f; o1[r] = 0.f; }

    for (int kt = 0; kt < Ss / 64; kt++) {
        const float* Kt = K + kt * 64 * HD;
        const float* Vt = V + kt * 64 * HD;
#pragma unroll
        for (int t = 0; t < 4; t++) {
            int lin = tid + t * 256;
            int row = lin >> 4;
            int c4 = (lin & 15) << 2;
            float4 kv = *(const float4*)(Kt + row * HD + c4);
            Ks[row * QK_STRIDE + c4 + 0] = kv.x;
            Ks[row * QK_STRIDE + c4 + 1] = kv.y;
            Ks[row * QK_STRIDE + c4 + 2] = kv.z;
            Ks[row * QK_STRIDE + c4 + 3] = kv.w;
            float4 vv = *(const float4*)(Vt + row * HD + c4);
            Vs[row * V_STRIDE + c4 + 0] = vv.x;
            Vs[row * V_STRIDE + c4 + 1] = vv.y;
            Vs[row * V_STRIDE + c4 + 2] = vv.z;
            Vs[row * V_STRIDE + c4 + 3] = vv.w;
        }
        __syncthreads();

        // scores: s[r][2l], s[r][2l+1]
        float s0[8], s1[8];
#pragma unroll
        for (int r = 0; r < 8; r++) { s0[r] = 0.f; s1[r] = 0.f; }
        const float* krow0 = Ks + (2 * lane) * QK_STRIDE;
        const float* krow1 = krow0 + QK_STRIDE;
        const float* qbase = Qs + warp * 8 * QK_STRIDE;
#pragma unroll 4
        for (int d = 0; d < 64; d++) {
            float k0 = krow0[d], k1 = krow1[d];
#pragma unroll
            for (int r = 0; r < 8; r++) {
                float q = qbase[r * QK_STRIDE + d];
                s0[r] += q * k0;
                s1[r] += q * k1;
            }
        }

        float alpha[8];
#pragma unroll
        for (int r = 0; r < 8; r++) {
            float mx = fmaxf(s0[r], s1[r]);
#pragma unroll
            for (int o2 = 16; o2; o2 >>= 1)
                mx = fmaxf(mx, __shfl_xor_sync(0xffffffffu, mx, o2));
            float mnew = fmaxf(m[r], mx);
            float p0 = __expf(s0[r] - mnew);
            float p1 = __expf(s1[r] - mnew);
            float rs = p0 + p1;
#pragma unroll
            for (int o2 = 16; o2; o2 >>= 1)
                rs += __shfl_xor_sync(0xffffffffu, rs, o2);
            alpha[r] = __expf(m[r] - mnew);
            l[r] = l[r] * alpha[r] + rs;
            m[r] = mnew;
            Ps[(warp * 8 + r) * QK_STRIDE + 2 * lane]     = p0;
            Ps[(warp * 8 + r) * QK_STRIDE + 2 * lane + 1] = p1;
        }
        __syncwarp();

        // O += P @ V
#pragma unroll
        for (int r = 0; r < 8; r++) {
            float a0 = o0[r] * alpha[r];
            float a1 = o1[r] * alpha[r];
            const float* prow = Ps + (warp * 8 + r) * QK_STRIDE;
#pragma unroll 4
            for (int c = 0; c < 64; c++) {
                float p = prow[c];
                float2 v = *(const float2*)(Vs + c * V_STRIDE + 2 * lane);
                a0 += p * v.x;
                a1 += p * v.y;
            }
            o0[r] = a0; o1[r] = a1;
        }
        __syncthreads();
    }

#pragma unroll
    for (int r = 0; r < 8; r++) {
        float inv = 1.f / l[r];
        int srow = qt * 64 + warp * 8 + r;
        *(float2*)(Og + ((size_t)(b * Ss + srow)) * Cc + h * HD + 2 * lane) =
            make_float2(o0[r] * inv, o1[r] * inv);
    }
}

// =====================================================================
extern "C" void kernel_launch(void* const* d_in, const int* in_sizes, int n_in,
                              void* d_out, int out_size)
{
    const float* x    = (const float*)d_in[0];
    const float* rope = (const float*)d_in[1];
    const float* wqkv = (const float*)d_in[2];
    const float* wout = (const float*)d_in[3];
    const float* qg   = (const float*)d_in[4];
    const float* qb   = (const float*)d_in[5];
    const float* kg   = (const float*)d_in[6];
    const float* kb   = (const float*)d_in[7];
    float* out = (float*)d_out;

    float *qkv, *q, *k, *v, *attn;
    cudaGetSymbolAddress((void**)&qkv,  g_qkv);
    cudaGetSymbolAddress((void**)&q,    g_q);
    cudaGetSymbolAddress((void**)&k,    g_k);
    cudaGetSymbolAddress((void**)&v,    g_v);
    cudaGetSymbolAddress((void**)&attn, g_attn);

    // 1) QKV projection: [4096,2048] x [6144,2048]^T -> [4096,6144]  (TF32 MMA)
    gemm_tf32_kernel<<<dim3(C3 / 128, BSs / 128), 256>>>(x, wqkv, qkv, BSs, C3, Cc);

    // 2) per-head LN + rotary + V copy -> [B,H,S,hd]
    lnrope_kernel<<<(Bb * Ss * Hh * 32) / 256, 256>>>(qkv, rope, qg, qb, kg, kb, q, k, v);

    // 3) attention
    cudaFuncSetAttribute(attn_kernel, cudaFuncAttributeMaxDynamicSharedMemorySize, ATTN_SMEM);
    attn_kernel<<<dim3(Ss / 64, Bb * Hh), 256, ATTN_SMEM>>>(q, k, v, attn);

    // 4) output projection: [4096,2048] x [2048,2048]^T -> [4096,2048]  (TF32 MMA)
    gemm_tf32_kernel<<<dim3(Cc / 128, BSs / 128), 256>>>(attn, wout, out, BSs, Cc, Cc);
}

// round 4
// speedup vs baseline: 1.9640x; 1.3679x over previous
#include <cuda_runtime.h>
#include <math.h>

// Problem dims (fixed for this problem instance)
#define Bb 2
#define Ss 2048
#define Cc 2048
#define HD 64
#define Hh 32              // Cc / HD
#define BSs (Bb * Ss)      // 4096
#define C3 (3 * Cc)        // 6144

// ---------------- scratch (no allocations allowed) ----------------
__device__ float g_qkv[(size_t)BSs * C3];        // [B,S,3C]
__device__ float g_q[(size_t)Bb * Hh * Ss * HD]; // [B,H,S,hd] (Q pre-scaled by 1/8)
__device__ float g_k[(size_t)Bb * Hh * Ss * HD];
__device__ float g_v[(size_t)Bb * Hh * Ss * HD];
__device__ float g_attn[(size_t)BSs * Cc];       // [B,S,C]

// ---------------- tf32 helpers ----------------
__device__ __forceinline__ unsigned f2tf(float f) {
    unsigned u;
    asm("cvt.rna.tf32.f32 %0, %1;" : "=r"(u) : "f"(f));
    return u;
}
// split x into hi (tf32 bits) and lo (tf32 bits of residual)
__device__ __forceinline__ void split_tf(float x, unsigned& hi, unsigned& lo) {
    hi = f2tf(x);
    lo = f2tf(x - __uint_as_float(hi));
}

__device__ __forceinline__ void mma_tf32(float c[4], const unsigned a[4],
                                         unsigned b0, unsigned b1) {
    asm volatile(
        "mma.sync.aligned.m16n8k8.row.col.f32.tf32.tf32.f32 "
        "{%0,%1,%2,%3}, {%4,%5,%6,%7}, {%8,%9}, {%0,%1,%2,%3};\n"
        : "+f"(c[0]), "+f"(c[1]), "+f"(c[2]), "+f"(c[3])
        : "r"(a[0]), "r"(a[1]), "r"(a[2]), "r"(a[3]), "r"(b0), "r"(b1));
}

// =====================================================================
// 3xTF32 tensor-core GEMM (NT): Cmat[m,n] = sum_k A[m,k] * W[n,k]
// Split precision: C += Ah*Bh + Al*Bh + Ah*Bl  (error ~ fp32 level)
// 128x128 CTA tile, BK=32, 256 threads = 8 warps, warp tile 64x32.
// =====================================================================
#define GS 36   // smem row stride in words (bank = 4*gid + tig, conflict-free)
#define GEMM_SMEM (4 * 128 * GS * 4)

__global__ __launch_bounds__(256) void gemm_3xtf32_kernel(
    const float* __restrict__ A, const float* __restrict__ W,
    float* __restrict__ Cmat, int M, int N, int K)
{
    extern __shared__ unsigned gsm[];
    unsigned* Ah = gsm;
    unsigned* Al = gsm + 128 * GS;
    unsigned* Bh = gsm + 2 * 128 * GS;
    unsigned* Bl = gsm + 3 * 128 * GS;

    const int tid  = threadIdx.x;
    const int m0   = blockIdx.y * 128;
    const int n0   = blockIdx.x * 128;
    const int warp = tid >> 5;
    const int lane = tid & 31;
    const int gid  = lane >> 2;
    const int tig  = lane & 3;
    const int wm   = (warp & 1) * 64;
    const int wn   = (warp >> 1) * 32;

    const int lr = tid >> 3;          // 0..31
    const int lk = (tid & 7) << 2;    // 0,4,...,28

    float c[4][4][4];
#pragma unroll
    for (int mt = 0; mt < 4; mt++)
#pragma unroll
        for (int nt = 0; nt < 4; nt++)
#pragma unroll
            for (int i = 0; i < 4; i++) c[mt][nt][i] = 0.f;

    const float* Ag = A + (size_t)(m0 + lr) * K + lk;
    const float* Bg = W + (size_t)(n0 + lr) * K + lk;

    float4 ra[4], rb[4];
#pragma unroll
    for (int p = 0; p < 4; p++) {
        ra[p] = *(const float4*)(Ag + (size_t)(p * 32) * K);
        rb[p] = *(const float4*)(Bg + (size_t)(p * 32) * K);
    }

#pragma unroll
    for (int p = 0; p < 4; p++) {
        uint4 h, l;
        split_tf(ra[p].x, h.x, l.x); split_tf(ra[p].y, h.y, l.y);
        split_tf(ra[p].z, h.z, l.z); split_tf(ra[p].w, h.w, l.w);
        *(uint4*)&Ah[(lr + p * 32) * GS + lk] = h;
        *(uint4*)&Al[(lr + p * 32) * GS + lk] = l;
        split_tf(rb[p].x, h.x, l.x); split_tf(rb[p].y, h.y, l.y);
        split_tf(rb[p].z, h.z, l.z); split_tf(rb[p].w, h.w, l.w);
        *(uint4*)&Bh[(lr + p * 32) * GS + lk] = h;
        *(uint4*)&Bl[(lr + p * 32) * GS + lk] = l;
    }

    const int ntiles = K >> 5;
    for (int t = 0; t < ntiles; t++) {
        if (t + 1 < ntiles) {
            const float* Ap = Ag + (size_t)(t + 1) * 32;
            const float* Bp = Bg + (size_t)(t + 1) * 32;
#pragma unroll
            for (int p = 0; p < 4; p++) {
                ra[p] = *(const float4*)(Ap + (size_t)(p * 32) * K);
                rb[p] = *(const float4*)(Bp + (size_t)(p * 32) * K);
            }
        }
        __syncthreads();

#pragma unroll
        for (int kk = 0; kk < 32; kk += 8) {
            unsigned bh[4][2], bl[4][2];
#pragma unroll
            for (int nt = 0; nt < 4; nt++) {
                int col = wn + nt * 8;
                bh[nt][0] = Bh[(col + gid) * GS + kk + tig];
                bh[nt][1] = Bh[(col + gid) * GS + kk + tig + 4];
                bl[nt][0] = Bl[(col + gid) * GS + kk + tig];
                bl[nt][1] = Bl[(col + gid) * GS + kk + tig + 4];
            }
#pragma unroll
            for (int mt = 0; mt < 4; mt++) {
                int row = wm + mt * 16;
                unsigned a[4];
                a[0] = Ah[(row + gid) * GS + kk + tig];
                a[1] = Ah[(row + gid + 8) * GS + kk + tig];
                a[2] = Ah[(row + gid) * GS + kk + tig + 4];
                a[3] = Ah[(row + gid + 8) * GS + kk + tig + 4];
#pragma unroll
                for (int nt = 0; nt < 4; nt++) {
                    mma_tf32(c[mt][nt], a, bh[nt][0], bh[nt][1]);
                    mma_tf32(c[mt][nt], a, bl[nt][0], bl[nt][1]);
                }
                a[0] = Al[(row + gid) * GS + kk + tig];
                a[1] = Al[(row + gid + 8) * GS + kk + tig];
                a[2] = Al[(row + gid) * GS + kk + tig + 4];
                a[3] = Al[(row + gid + 8) * GS + kk + tig + 4];
#pragma unroll
                for (int nt = 0; nt < 4; nt++)
                    mma_tf32(c[mt][nt], a, bh[nt][0], bh[nt][1]);
            }
        }
        __syncthreads();

        if (t + 1 < ntiles) {
#pragma unroll
            for (int p = 0; p < 4; p++) {
                uint4 h, l;
                split_tf(ra[p].x, h.x, l.x); split_tf(ra[p].y, h.y, l.y);
                split_tf(ra[p].z, h.z, l.z); split_tf(ra[p].w, h.w, l.w);
                *(uint4*)&Ah[(lr + p * 32) * GS + lk] = h;
                *(uint4*)&Al[(lr + p * 32) * GS + lk] = l;
                split_tf(rb[p].x, h.x, l.x); split_tf(rb[p].y, h.y, l.y);
                split_tf(rb[p].z, h.z, l.z); split_tf(rb[p].w, h.w, l.w);
                *(uint4*)&Bh[(lr + p * 32) * GS + lk] = h;
                *(uint4*)&Bl[(lr + p * 32) * GS + lk] = l;
            }
        }
    }

#pragma unroll
    for (int mt = 0; mt < 4; mt++) {
        int row0 = m0 + wm + mt * 16 + gid;
        int row1 = row0 + 8;
#pragma unroll
        for (int nt = 0; nt < 4; nt++) {
            int col = n0 + wn + nt * 8 + tig * 2;
            *(float2*)(Cmat + (size_t)row0 * N + col) = make_float2(c[mt][nt][0], c[mt][nt][1]);
            *(float2*)(Cmat + (size_t)row1 * N + col) = make_float2(c[mt][nt][2], c[mt][nt][3]);
        }
    }
}

// =====================================================================
// Fused LayerNorm (per-head) + rotary + V copy. One warp per (b,s,h).
// Q pre-scaled by 1/8. Output layout: [B,H,S,hd].
// =====================================================================
__global__ __launch_bounds__(256) void lnrope_kernel(
    const float* __restrict__ qkv, const float* __restrict__ rope,
    const float* __restrict__ qg, const float* __restrict__ qb,
    const float* __restrict__ kg, const float* __restrict__ kb,
    float* __restrict__ Qo, float* __restrict__ Ko, float* __restrict__ Vo)
{
    int gw   = (blockIdx.x * blockDim.x + threadIdx.x) >> 5;
    int lane = threadIdx.x & 31;
    if (gw >= Bb * Ss * Hh) return;
    int h = gw % Hh;
    int s = (gw / Hh) % Ss;
    int b = gw / (Hh * Ss);

    const float* base = qkv + ((size_t)(b * Ss + s)) * C3 + h * (3 * HD);
    float4 r4 = *(const float4*)(rope + (size_t)s * 128 + lane * 4);
    size_t obase = (((size_t)(b * Hh + h)) * Ss + s) * HD + 2 * lane;

    float gq0 = qg[2 * lane], gq1 = qg[2 * lane + 1];
    float bq0 = qb[2 * lane], bq1 = qb[2 * lane + 1];
    float gk0 = kg[2 * lane], gk1 = kg[2 * lane + 1];
    float bk0 = kb[2 * lane], bk1 = kb[2 * lane + 1];

    {
        float2 x2 = *(const float2*)(base + 2 * lane);
        float sum = x2.x + x2.y;
#pragma unroll
        for (int o = 16; o; o >>= 1) sum += __shfl_xor_sync(0xffffffffu, sum, o);
        float mean = sum * (1.f / 64.f);
        float d0 = x2.x - mean, d1 = x2.y - mean;
        float vs = d0 * d0 + d1 * d1;
#pragma unroll
        for (int o = 16; o; o >>= 1) vs += __shfl_xor_sync(0xffffffffu, vs, o);
        float inv = rsqrtf(vs * (1.f / 64.f) + 1e-5f);
        float n0 = d0 * inv * gq0 + bq0;
        float n1 = d1 * inv * gq1 + bq1;
        float o0 = r4.x * n0 + r4.y * n1;
        float o1 = r4.z * n0 + r4.w * n1;
        *(float2*)(Qo + obase) = make_float2(o0 * 0.125f, o1 * 0.125f);
    }
    {
        float2 x2 = *(const float2*)(base + HD + 2 * lane);
        float sum = x2.x + x2.y;
#pragma unroll
        for (int o = 16; o; o >>= 1) sum += __shfl_xor_sync(0xffffffffu, sum, o);
        float mean = sum * (1.f / 64.f);
        float d0 = x2.x - mean, d1 = x2.y - mean;
        float vs = d0 * d0 + d1 * d1;
#pragma unroll
        for (int o = 16; o; o >>= 1) vs += __shfl_xor_sync(0xffffffffu, vs, o);
        float inv = rsqrtf(vs * (1.f / 64.f) + 1e-5f);
        float n0 = d0 * inv * gk0 + bk0;
        float n1 = d1 * inv * gk1 + bk1;
        float o0 = r4.x * n0 + r4.y * n1;
        float o1 = r4.z * n0 + r4.w * n1;
        *(float2*)(Ko + obase) = make_float2(o0, o1);
    }
    {
        float2 x2 = *(const float2*)(base + 2 * HD + 2 * lane);
        *(float2*)(Vo + obase) = x2;
    }
}

// =====================================================================
// Tensor-core flash attention (tf32).
// CTA: 128 q-rows, k-tiles of 64. 8 warps, each owns 16 q-rows (full width
// of scores -> no cross-warp softmax reduction).
// QK^T uses 3-term tf32 split (scores ~ fp32 exact).
// PV uses single tf32 (P_hi x V_hi) -> error ~2e-4 in a weighted average.
// All smem tiles use stride 68 (== 4 mod 32): fragment loads conflict-free.
// =====================================================================
#define AST 68
#define OFF_QH 0
#define OFF_QL (128 * AST)
#define OFF_KH (2 * 128 * AST)
#define OFF_KL (OFF_KH + 64 * AST)
#define OFF_VT (OFF_KL + 64 * AST)
#define OFF_PH (OFF_VT + 64 * AST)
#define ATTN_WORDS (OFF_PH + 128 * AST)
#define ATTN_SMEM (ATTN_WORDS * 4)

__global__ __launch_bounds__(256) void attn_tc_kernel(
    const float* __restrict__ Qg, const float* __restrict__ Kg,
    const float* __restrict__ Vg, float* __restrict__ Og)
{
    extern __shared__ unsigned asm_[];
    unsigned* Qh = asm_ + OFF_QH;
    unsigned* Ql = asm_ + OFF_QL;
    unsigned* Kh = asm_ + OFF_KH;
    unsigned* Kl = asm_ + OFF_KL;
    unsigned* Vt = asm_ + OFF_VT;   // V^T: [d][kv]
    unsigned* Ph = asm_ + OFF_PH;

    const int bh = blockIdx.y;
    const int b  = bh >> 5;
    const int h  = bh & (Hh - 1);
    const int qt = blockIdx.x;

    const float* Q = Qg + ((size_t)bh * Ss + qt * 128) * HD;
    const float* K = Kg + (size_t)bh * Ss * HD;
    const float* V = Vg + (size_t)bh * Ss * HD;

    const int tid  = threadIdx.x;
    const int warp = tid >> 5, lane = tid & 31;
    const int gid  = lane >> 2, tig = lane & 3;
    const int r0   = warp * 16;

    // ---- load Q tile (128x64) as hi/lo; STS conflict-free (rows across lanes)
#pragma unroll
    for (int j = 0; j < 8; j++) {
        int lin = tid + j * 256;          // 0..2047 float4s
        int row = lin & 127;
        int c4  = (lin >> 7) << 2;
        float4 v = *(const float4*)(Q + (size_t)row * HD + c4);
        unsigned hx, lx;
        split_tf(v.x, hx, lx); Qh[row * AST + c4 + 0] = hx; Ql[row * AST + c4 + 0] = lx;
        split_tf(v.y, hx, lx); Qh[row * AST + c4 + 1] = hx; Ql[row * AST + c4 + 1] = lx;
        split_tf(v.z, hx, lx); Qh[row * AST + c4 + 2] = hx; Ql[row * AST + c4 + 2] = lx;
        split_tf(v.w, hx, lx); Qh[row * AST + c4 + 3] = hx; Ql[row * AST + c4 + 3] = lx;
    }

    float o[8][4];
#pragma unroll
    for (int nt = 0; nt < 8; nt++)
#pragma unroll
        for (int i = 0; i < 4; i++) o[nt][i] = 0.f;
    float m0 = -1e30f, m1 = -1e30f, l0 = 0.f, l1 = 0.f;

    for (int kt = 0; kt < Ss / 64; kt++) {
        const float* Kt = K + (size_t)kt * 64 * HD;
        const float* Vtile = V + (size_t)kt * 64 * HD;

        // ---- K tile (64x64) hi/lo
#pragma unroll
        for (int j = 0; j < 4; j++) {
            int lin = tid + j * 256;      // 0..1023 float4s
            int row = lin & 63;
            int c4  = (lin >> 6) << 2;
            float4 v = *(const float4*)(Kt + (size_t)row * HD + c4);
            unsigned hx, lx;
            split_tf(v.x, hx, lx); Kh[row * AST + c4 + 0] = hx; Kl[row * AST + c4 + 0] = lx;
            split_tf(v.y, hx, lx); Kh[row * AST + c4 + 1] = hx; Kl[row * AST + c4 + 1] = lx;
            split_tf(v.z, hx, lx); Kh[row * AST + c4 + 2] = hx; Kl[row * AST + c4 + 2] = lx;
            split_tf(v.w, hx, lx); Kh[row * AST + c4 + 3] = hx; Kl[row * AST + c4 + 3] = lx;
        }
        // ---- V tile transposed (hi only): Vt[d][kv]
#pragma unroll
        for (int j = 0; j < 4; j++) {
            int row = warp * 8 + (lane & 7);          // kv row
            int c4  = j * 16 + ((lane >> 3) << 2);    // d
            float4 v = *(const float4*)(Vtile + (size_t)row * HD + c4);
            Vt[(c4 + 0) * AST + row] = f2tf(v.x);
            Vt[(c4 + 1) * AST + row] = f2tf(v.y);
            Vt[(c4 + 2) * AST + row] = f2tf(v.z);
            Vt[(c4 + 3) * AST + row] = f2tf(v.w);
        }
        __syncthreads();

        // ---- S = Q K^T  (3-term split)
        float s[8][4];
#pragma unroll
        for (int nt = 0; nt < 8; nt++)
#pragma unroll
            for (int i = 0; i < 4; i++) s[nt][i] = 0.f;

#pragma unroll
        for (int kk = 0; kk < 64; kk += 8) {
            unsigned ah[4], al[4];
            ah[0] = Qh[(r0 + gid) * AST + kk + tig];
            ah[1] = Qh[(r0 + gid + 8) * AST + kk + tig];
            ah[2] = Qh[(r0 + gid) * AST + kk + tig + 4];
            ah[3] = Qh[(r0 + gid + 8) * AST + kk + tig + 4];
            al[0] = Ql[(r0 + gid) * AST + kk + tig];
            al[1] = Ql[(r0 + gid + 8) * AST + kk + tig];
            al[2] = Ql[(r0 + gid) * AST + kk + tig + 4];
            al[3] = Ql[(r0 + gid + 8) * AST + kk + tig + 4];
#pragma unroll
            for (int nt = 0; nt < 8; nt++) {
                unsigned bh0 = Kh[(8 * nt + gid) * AST + kk + tig];
                unsigned bh1 = Kh[(8 * nt + gid) * AST + kk + tig + 4];
                unsigned bl0 = Kl[(8 * nt + gid) * AST + kk + tig];
                unsigned bl1 = Kl[(8 * nt + gid) * AST + kk + tig + 4];
                mma_tf32(s[nt], ah, bh0, bh1);
                mma_tf32(s[nt], al, bh0, bh1);
                mma_tf32(s[nt], ah, bl0, bl1);
            }
        }

        // ---- online softmax (rows gid and gid+8 of this warp's 16)
        float rmax0 = -1e30f, rmax1 = -1e30f;
#pragma unroll
        for (int nt = 0; nt < 8; nt++) {
            rmax0 = fmaxf(rmax0, fmaxf(s[nt][0], s[nt][1]));
            rmax1 = fmaxf(rmax1, fmaxf(s[nt][2], s[nt][3]));
        }
#pragma unroll
        for (int off = 1; off <= 2; off <<= 1) {
            rmax0 = fmaxf(rmax0, __shfl_xor_sync(0xffffffffu, rmax0, off));
            rmax1 = fmaxf(rmax1, __shfl_xor_sync(0xffffffffu, rmax1, off));
        }
        float mn0 = fmaxf(m0, rmax0), mn1 = fmaxf(m1, rmax1);
        float alpha0 = __expf(m0 - mn0), alpha1 = __expf(m1 - mn1);
        float sum0 = 0.f, sum1 = 0.f;
#pragma unroll
        for (int nt = 0; nt < 8; nt++) {
            float p0 = __expf(s[nt][0] - mn0);
            float p1 = __expf(s[nt][1] - mn0);
            float p2 = __expf(s[nt][2] - mn1);
            float p3 = __expf(s[nt][3] - mn1);
            sum0 += p0 + p1; sum1 += p2 + p3;
            Ph[(r0 + gid) * AST + 8 * nt + 2 * tig]     = f2tf(p0);
            Ph[(r0 + gid) * AST + 8 * nt + 2 * tig + 1] = f2tf(p1);
            Ph[(r0 + gid + 8) * AST + 8 * nt + 2 * tig]     = f2tf(p2);
            Ph[(r0 + gid + 8) * AST + 8 * nt + 2 * tig + 1] = f2tf(p3);
        }
#pragma unroll
        for (int off = 1; off <= 2; off <<= 1) {
            sum0 += __shfl_xor_sync(0xffffffffu, sum0, off);
            sum1 += __shfl_xor_sync(0xffffffffu, sum1, off);
        }
        l0 = l0 * alpha0 + sum0;
        l1 = l1 * alpha1 + sum1;
        m0 = mn0; m1 = mn1;
#pragma unroll
        for (int nt = 0; nt < 8; nt++) {
            o[nt][0] *= alpha0; o[nt][1] *= alpha0;
            o[nt][2] *= alpha1; o[nt][3] *= alpha1;
        }
        __syncwarp();

        // ---- O += P V  (single tf32; warp reads only its own P rows)
#pragma unroll
        for (int kk = 0; kk < 64; kk += 8) {
            unsigned a[4];
            a[0] = Ph[(r0 + gid) * AST + kk + tig];
            a[1] = Ph[(r0 + gid + 8) * AST + kk + tig];
            a[2] = Ph[(r0 + gid) * AST + kk + tig + 4];
            a[3] = Ph[(r0 + gid + 8) * AST + kk + tig + 4];
#pragma unroll
            for (int nt = 0; nt < 8; nt++) {
                unsigned b0 = Vt[(8 * nt + gid) * AST + kk + tig];
                unsigned b1 = Vt[(8 * nt + gid) * AST + kk + tig + 4];
                mma_tf32(o[nt], a, b0, b1);
            }
        }
        __syncthreads();
    }

    // ---- epilogue: normalize and write [B,S,C]
    float inv0 = 1.f / l0, inv1 = 1.f / l1;
    int row0 = qt * 128 + r0 + gid;
    int row1 = row0 + 8;
    float* O0 = Og + ((size_t)(b * Ss + row0)) * Cc + h * HD;
    float* O1 = Og + ((size_t)(b * Ss + row1)) * Cc + h * HD;
#pragma unroll
    for (int nt = 0; nt < 8; nt++) {
        *(float2*)(O0 + 8 * nt + 2 * tig) = make_float2(o[nt][0] * inv0, o[nt][1] * inv0);
        *(float2*)(O1 + 8 * nt + 2 * tig) = make_float2(o[nt][2] * inv1, o[nt][3] * inv1);
    }
}

// =====================================================================
extern "C" void kernel_launch(void* const* d_in, const int* in_sizes, int n_in,
                              void* d_out, int out_size)
{
    const float* x    = (const float*)d_in[0];
    const float* rope = (const float*)d_in[1];
    const float* wqkv = (const float*)d_in[2];
    const float* wout = (const float*)d_in[3];
    const float* qg   = (const float*)d_in[4];
    const float* qb   = (const float*)d_in[5];
    const float* kg   = (const float*)d_in[6];
    const float* kb   = (const float*)d_in[7];
    float* out = (float*)d_out;

    float *qkv, *q, *k, *v, *attn;
    cudaGetSymbolAddress((void**)&qkv,  g_qkv);
    cudaGetSymbolAddress((void**)&q,    g_q);
    cudaGetSymbolAddress((void**)&k,    g_k);
    cudaGetSymbolAddress((void**)&v,    g_v);
    cudaGetSymbolAddress((void**)&attn, g_attn);

    cudaFuncSetAttribute(gemm_3xtf32_kernel, cudaFuncAttributeMaxDynamicSharedMemorySize, GEMM_SMEM);
    cudaFuncSetAttribute(attn_tc_kernel, cudaFuncAttributeMaxDynamicSharedMemorySize, ATTN_SMEM);

    // 1) QKV projection (3xTF32)
    gemm_3xtf32_kernel<<<dim3(C3 / 128, BSs / 128), 256, GEMM_SMEM>>>(x, wqkv, qkv, BSs, C3, Cc);

    // 2) per-head LN + rotary + V copy -> [B,H,S,hd]
    lnrope_kernel<<<(Bb * Ss * Hh * 32) / 256, 256>>>(qkv, rope, qg, qb, kg, kb, q, k, v);

    // 3) attention (tensor-core flash)
    attn_tc_kernel<<<dim3(Ss / 128, Bb * Hh), 256, ATTN_SMEM>>>(q, k, v, attn);

    // 4) output projection (3xTF32)
    gemm_3xtf32_kernel<<<dim3(Cc / 128, BSs / 128), 256, GEMM_SMEM>>>(attn, wout, out, BSs, Cc, Cc);
}

// round 5
// speedup vs baseline: 1.9884x; 1.0124x over previous
#include <cuda_runtime.h>
#include <math.h>

// Problem dims (fixed for this problem instance)
#define Bb 2
#define Ss 2048
#define Cc 2048
#define HD 64
#define Hh 32              // Cc / HD
#define BSs (Bb * Ss)      // 4096
#define C3 (3 * Cc)        // 6144

// ---------------- scratch (no allocations allowed) ----------------
__device__ float g_qkv[(size_t)BSs * C3];        // [B,S,3C]
__device__ float g_q[(size_t)Bb * Hh * Ss * HD]; // [B,H,S,hd] (Q pre-scaled by 1/8)
__device__ float g_k[(size_t)Bb * Hh * Ss * HD];
__device__ float g_v[(size_t)Bb * Hh * Ss * HD];
__device__ float g_attn[(size_t)BSs * Cc];       // [B,S,C]

// ---------------- tf32 helpers ----------------
__device__ __forceinline__ unsigned f2tf(float f) {
    unsigned u;
    asm("cvt.rna.tf32.f32 %0, %1;" : "=r"(u) : "f"(f));
    return u;
}
__device__ __forceinline__ void split_tf(float x, unsigned& hi, unsigned& lo) {
    hi = f2tf(x);
    lo = f2tf(x - __uint_as_float(hi));
}
__device__ __forceinline__ void mma_tf32(float c[4], const unsigned a[4],
                                         unsigned b0, unsigned b1) {
    asm volatile(
        "mma.sync.aligned.m16n8k8.row.col.f32.tf32.tf32.f32 "
        "{%0,%1,%2,%3}, {%4,%5,%6,%7}, {%8,%9}, {%0,%1,%2,%3};\n"
        : "+f"(c[0]), "+f"(c[1]), "+f"(c[2]), "+f"(c[3])
        : "r"(a[0]), "r"(a[1]), "r"(a[2]), "r"(a[3]), "r"(b0), "r"(b1));
}

// ---------------- cp.async helpers ----------------
__device__ __forceinline__ void cp_async16(void* smem_dst, const void* gsrc) {
    unsigned sa = (unsigned)__cvta_generic_to_shared(smem_dst);
    asm volatile("cp.async.ca.shared.global [%0], [%1], 16;\n"
                 :: "r"(sa), "l"(gsrc) : "memory");
}
__device__ __forceinline__ void cp_commit() {
    asm volatile("cp.async.commit_group;\n" ::: "memory");
}
template <int N>
__device__ __forceinline__ void cp_wait_group() {
    asm volatile("cp.async.wait_group %0;\n" :: "n"(N) : "memory");
}

// =====================================================================
// 3xTF32 tensor-core GEMM (NT): Cmat[m,n] = sum_k A[m,k] * W[n,k]
// C += Ah*Bh + Al*Bh + Ah*Bl (split computed on-the-fly at fragment load).
// Raw fp32 smem tiles, cp.async, 2-stage double buffer.
// 128x128 CTA tile, BK=32, 256 threads = 8 warps, warp tile 64x32.
// =====================================================================
#define GS 36   // smem row stride in words (bank = 4*gid + tig, conflict-free)
#define GEMM_SMEM (4 * 128 * GS * 4)   // 2 stages x (A,B) raw fp32

__global__ __launch_bounds__(256, 2) void gemm_3xtf32_kernel(
    const float* __restrict__ A, const float* __restrict__ W,
    float* __restrict__ Cmat, int M, int N, int K)
{
    extern __shared__ float gsm[];
    float* Abuf[2] = { gsm,              gsm + 2 * 128 * GS };
    float* Bbuf[2] = { gsm + 128 * GS,   gsm + 3 * 128 * GS };

    const int tid  = threadIdx.x;
    const int m0   = blockIdx.y * 128;
    const int n0   = blockIdx.x * 128;
    const int warp = tid >> 5;
    const int lane = tid & 31;
    const int gid  = lane >> 2;
    const int tig  = lane & 3;
    const int wm   = (warp & 1) * 64;
    const int wn   = (warp >> 1) * 32;

    const int lr = tid >> 3;          // 0..31
    const int lk = (tid & 7) << 2;    // 0,4,...,28

    float c[4][4][4];
#pragma unroll
    for (int mt = 0; mt < 4; mt++)
#pragma unroll
        for (int nt = 0; nt < 4; nt++)
#pragma unroll
            for (int i = 0; i < 4; i++) c[mt][nt][i] = 0.f;

    const float* Ag = A + (size_t)(m0 + lr) * K + lk;
    const float* Bg = W + (size_t)(n0 + lr) * K + lk;

    const int ntiles = K >> 5;

    // prologue: stage 0 loads for tile 0
    {
        float* As = Abuf[0];
        float* Bs = Bbuf[0];
#pragma unroll
        for (int p = 0; p < 4; p++) {
            cp_async16(&As[(lr + p * 32) * GS + lk], Ag + (size_t)(p * 32) * K);
            cp_async16(&Bs[(lr + p * 32) * GS + lk], Bg + (size_t)(p * 32) * K);
        }
        cp_commit();
    }

    for (int t = 0; t < ntiles; t++) {
        const int st = t & 1;
        // issue loads for t+1 into the other stage, then wait for tile t
        if (t + 1 < ntiles) {
            float* As = Abuf[st ^ 1];
            float* Bs = Bbuf[st ^ 1];
            const float* Ap = Ag + (size_t)(t + 1) * 32;
            const float* Bp = Bg + (size_t)(t + 1) * 32;
#pragma unroll
            for (int p = 0; p < 4; p++) {
                cp_async16(&As[(lr + p * 32) * GS + lk], Ap + (size_t)(p * 32) * K);
                cp_async16(&Bs[(lr + p * 32) * GS + lk], Bp + (size_t)(p * 32) * K);
            }
            cp_commit();
            cp_wait_group<1>();
        } else {
            cp_wait_group<0>();
        }
        __syncthreads();

        const float* As = Abuf[st];
        const float* Bs = Bbuf[st];

#pragma unroll
        for (int kk = 0; kk < 32; kk += 8) {
            unsigned bh[4][2], bl[4][2];
#pragma unroll
            for (int nt = 0; nt < 4; nt++) {
                int col = wn + nt * 8;
                float x0 = Bs[(col + gid) * GS + kk + tig];
                float x1 = Bs[(col + gid) * GS + kk + tig + 4];
                split_tf(x0, bh[nt][0], bl[nt][0]);
                split_tf(x1, bh[nt][1], bl[nt][1]);
            }
#pragma unroll
            for (int mt = 0; mt < 4; mt++) {
                int row = wm + mt * 16;
                float a0 = As[(row + gid) * GS + kk + tig];
                float a1 = As[(row + gid + 8) * GS + kk + tig];
                float a2 = As[(row + gid) * GS + kk + tig + 4];
                float a3 = As[(row + gid + 8) * GS + kk + tig + 4];
                unsigned ah[4], al[4];
                split_tf(a0, ah[0], al[0]);
                split_tf(a1, ah[1], al[1]);
                split_tf(a2, ah[2], al[2]);
                split_tf(a3, ah[3], al[3]);
#pragma unroll
                for (int nt = 0; nt < 4; nt++) {
                    mma_tf32(c[mt][nt], ah, bh[nt][0], bh[nt][1]);
                    mma_tf32(c[mt][nt], al, bh[nt][0], bh[nt][1]);
                    mma_tf32(c[mt][nt], ah, bl[nt][0], bl[nt][1]);
                }
            }
        }
        __syncthreads();
    }

#pragma unroll
    for (int mt = 0; mt < 4; mt++) {
        int row0 = m0 + wm + mt * 16 + gid;
        int row1 = row0 + 8;
#pragma unroll
        for (int nt = 0; nt < 4; nt++) {
            int col = n0 + wn + nt * 8 + tig * 2;
            *(float2*)(Cmat + (size_t)row0 * N + col) = make_float2(c[mt][nt][0], c[mt][nt][1]);
            *(float2*)(Cmat + (size_t)row1 * N + col) = make_float2(c[mt][nt][2], c[mt][nt][3]);
        }
    }
}

// =====================================================================
// Fused LayerNorm (per-head) + rotary + V copy. One warp per (b,s,h).
// Q pre-scaled by 1/8. Output layout: [B,H,S,hd].
// =====================================================================
__global__ __launch_bounds__(256) void lnrope_kernel(
    const float* __restrict__ qkv, const float* __restrict__ rope,
    const float* __restrict__ qg, const float* __restrict__ qb,
    const float* __restrict__ kg, const float* __restrict__ kb,
    float* __restrict__ Qo, float* __restrict__ Ko, float* __restrict__ Vo)
{
    int gw   = (blockIdx.x * blockDim.x + threadIdx.x) >> 5;
    int lane = threadIdx.x & 31;
    if (gw >= Bb * Ss * Hh) return;
    int h = gw % Hh;
    int s = (gw / Hh) % Ss;
    int b = gw / (Hh * Ss);

    const float* base = qkv + ((size_t)(b * Ss + s)) * C3 + h * (3 * HD);
    float4 r4 = *(const float4*)(rope + (size_t)s * 128 + lane * 4);
    size_t obase = (((size_t)(b * Hh + h)) * Ss + s) * HD + 2 * lane;

    float gq0 = qg[2 * lane], gq1 = qg[2 * lane + 1];
    float bq0 = qb[2 * lane], bq1 = qb[2 * lane + 1];
    float gk0 = kg[2 * lane], gk1 = kg[2 * lane + 1];
    float bk0 = kb[2 * lane], bk1 = kb[2 * lane + 1];

    {
        float2 x2 = *(const float2*)(base + 2 * lane);
        float sum = x2.x + x2.y;
#pragma unroll
        for (int o = 16; o; o >>= 1) sum += __shfl_xor_sync(0xffffffffu, sum, o);
        float mean = sum * (1.f / 64.f);
        float d0 = x2.x - mean, d1 = x2.y - mean;
        float vs = d0 * d0 + d1 * d1;
#pragma unroll
        for (int o = 16; o; o >>= 1) vs += __shfl_xor_sync(0xffffffffu, vs, o);
        float inv = rsqrtf(vs * (1.f / 64.f) + 1e-5f);
        float n0 = d0 * inv * gq0 + bq0;
        float n1 = d1 * inv * gq1 + bq1;
        float o0 = r4.x * n0 + r4.y * n1;
        float o1 = r4.z * n0 + r4.w * n1;
        *(float2*)(Qo + obase) = make_float2(o0 * 0.125f, o1 * 0.125f);
    }
    {
        float2 x2 = *(const float2*)(base + HD + 2 * lane);
        float sum = x2.x + x2.y;
#pragma unroll
        for (int o = 16; o; o >>= 1) sum += __shfl_xor_sync(0xffffffffu, sum, o);
        float mean = sum * (1.f / 64.f);
        float d0 = x2.x - mean, d1 = x2.y - mean;
        float vs = d0 * d0 + d1 * d1;
#pragma unroll
        for (int o = 16; o; o >>= 1) vs += __shfl_xor_sync(0xffffffffu, vs, o);
        float inv = rsqrtf(vs * (1.f / 64.f) + 1e-5f);
        float n0 = d0 * inv * gk0 + bk0;
        float n1 = d1 * inv * gk1 + bk1;
        float o0 = r4.x * n0 + r4.y * n1;
        float o1 = r4.z * n0 + r4.w * n1;
        *(float2*)(Ko + obase) = make_float2(o0, o1);
    }
    {
        float2 x2 = *(const float2*)(base + 2 * HD + 2 * lane);
        *(float2*)(Vo + obase) = x2;
    }
}

// =====================================================================
// Tensor-core flash attention (tf32).
// CTA: 128 q-rows, k-tiles of 64. 8 warps, each owns 16 q-rows.
// QK^T: 3-term tf32 split. PV: single tf32.
// Smem stride 68 (== 4 mod 32): fragment loads conflict-free.
// =====================================================================
#define AST 68
#define OFF_QH 0
#define OFF_QL (128 * AST)
#define OFF_KH (2 * 128 * AST)
#define OFF_KL (OFF_KH + 64 * AST)
#define OFF_VT (OFF_KL + 64 * AST)
#define OFF_PH (OFF_VT + 64 * AST)
#define ATTN_WORDS (OFF_PH + 128 * AST)
#define ATTN_SMEM (ATTN_WORDS * 4)

__global__ __launch_bounds__(256) void attn_tc_kernel(
    const float* __restrict__ Qg, const float* __restrict__ Kg,
    const float* __restrict__ Vg, float* __restrict__ Og)
{
    extern __shared__ unsigned asm_[];
    unsigned* Qh = asm_ + OFF_QH;
    unsigned* Ql = asm_ + OFF_QL;
    unsigned* Kh = asm_ + OFF_KH;
    unsigned* Kl = asm_ + OFF_KL;
    unsigned* Vt = asm_ + OFF_VT;   // V^T: [d][kv]
    unsigned* Ph = asm_ + OFF_PH;

    const int bh = blockIdx.y;
    const int b  = bh >> 5;
    const int h  = bh & (Hh - 1);
    const int qt = blockIdx.x;

    const float* Q = Qg + ((size_t)bh * Ss + qt * 128) * HD;
    const float* K = Kg + (size_t)bh * Ss * HD;
    const float* V = Vg + (size_t)bh * Ss * HD;

    const int tid  = threadIdx.x;
    const int warp = tid >> 5, lane = tid & 31;
    const int gid  = lane >> 2, tig = lane & 3;
    const int r0   = warp * 16;

#pragma unroll
    for (int j = 0; j < 8; j++) {
        int lin = tid + j * 256;
        int row = lin & 127;
        int c4  = (lin >> 7) << 2;
        float4 v = *(const float4*)(Q + (size_t)row * HD + c4);
        unsigned hx, lx;
        split_tf(v.x, hx, lx); Qh[row * AST + c4 + 0] = hx; Ql[row * AST + c4 + 0] = lx;
        split_tf(v.y, hx, lx); Qh[row * AST + c4 + 1] = hx; Ql[row * AST + c4 + 1] = lx;
        split_tf(v.z, hx, lx); Qh[row * AST + c4 + 2] = hx; Ql[row * AST + c4 + 2] = lx;
        split_tf(v.w, hx, lx); Qh[row * AST + c4 + 3] = hx; Ql[row * AST + c4 + 3] = lx;
    }

    float o[8][4];
#pragma unroll
    for (int nt = 0; nt < 8; nt++)
#pragma unroll
        for (int i = 0; i < 4; i++) o[nt][i] = 0.f;
    float m0 = -1e30f, m1 = -1e30f, l0 = 0.f, l1 = 0.f;

    for (int kt = 0; kt < Ss / 64; kt++) {
        const float* Kt = K + (size_t)kt * 64 * HD;
        const float* Vtile = V + (size_t)kt * 64 * HD;

#pragma unroll
        for (int j = 0; j < 4; j++) {
            int lin = tid + j * 256;
            int row = lin & 63;
            int c4  = (lin >> 6) << 2;
            float4 v = *(const float4*)(Kt + (size_t)row * HD + c4);
            unsigned hx, lx;
            split_tf(v.x, hx, lx); Kh[row * AST + c4 + 0] = hx; Kl[row * AST + c4 + 0] = lx;
            split_tf(v.y, hx, lx); Kh[row * AST + c4 + 1] = hx; Kl[row * AST + c4 + 1] = lx;
            split_tf(v.z, hx, lx); Kh[row * AST + c4 + 2] = hx; Kl[row * AST + c4 + 2] = lx;
            split_tf(v.w, hx, lx); Kh[row * AST + c4 + 3] = hx; Kl[row * AST + c4 + 3] = lx;
        }
#pragma unroll
        for (int j = 0; j < 4; j++) {
            int row = warp * 8 + (lane & 7);
            int c4  = j * 16 + ((lane >> 3) << 2);
            float4 v = *(const float4*)(Vtile + (size_t)row * HD + c4);
            Vt[(c4 + 0) * AST + row] = f2tf(v.x);
            Vt[(c4 + 1) * AST + row] = f2tf(v.y);
            Vt[(c4 + 2) * AST + row] = f2tf(v.z);
            Vt[(c4 + 3) * AST + row] = f2tf(v.w);
        }
        __syncthreads();

        float s[8][4];
#pragma unroll
        for (int nt = 0; nt < 8; nt++)
#pragma unroll
            for (int i = 0; i < 4; i++) s[nt][i] = 0.f;

#pragma unroll
        for (int kk = 0; kk < 64; kk += 8) {
            unsigned ah[4], al[4];
            ah[0] = Qh[(r0 + gid) * AST + kk + tig];
            ah[1] = Qh[(r0 + gid + 8) * AST + kk + tig];
            ah[2] = Qh[(r0 + gid) * AST + kk + tig + 4];
            ah[3] = Qh[(r0 + gid + 8) * AST + kk + tig + 4];
            al[0] = Ql[(r0 + gid) * AST + kk + tig];
            al[1] = Ql[(r0 + gid + 8) * AST + kk + tig];
            al[2] = Ql[(r0 + gid) * AST + kk + tig + 4];
            al[3] = Ql[(r0 + gid + 8) * AST + kk + tig + 4];
#pragma unroll
            for (int nt = 0; nt < 8; nt++) {
                unsigned bh0 = Kh[(8 * nt + gid) * AST + kk + tig];
                unsigned bh1 = Kh[(8 * nt + gid) * AST + kk + tig + 4];
                unsigned bl0 = Kl[(8 * nt + gid) * AST + kk + tig];
                unsigned bl1 = Kl[(8 * nt + gid) * AST + kk + tig + 4];
                mma_tf32(s[nt], ah, bh0, bh1);
                mma_tf32(s[nt], al, bh0, bh1);
                mma_tf32(s[nt], ah, bl0, bl1);
            }
        }

        float rmax0 = -1e30f, rmax1 = -1e30f;
#pragma unroll
        for (int nt = 0; nt < 8; nt++) {
            rmax0 = fmaxf(rmax0, fmaxf(s[nt][0], s[nt][1]));
            rmax1 = fmaxf(rmax1, fmaxf(s[nt][2], s[nt][3]));
        }
#pragma unroll
        for (int off = 1; off <= 2; off <<= 1) {
            rmax0 = fmaxf(rmax0, __shfl_xor_sync(0xffffffffu, rmax0, off));
            rmax1 = fmaxf(rmax1, __shfl_xor_sync(0xffffffffu, rmax1, off));
        }
        float mn0 = fmaxf(m0, rmax0), mn1 = fmaxf(m1, rmax1);
        float alpha0 = __expf(m0 - mn0), alpha1 = __expf(m1 - mn1);
        float sum0 = 0.f, sum1 = 0.f;
#pragma unroll
        for (int nt = 0; nt < 8; nt++) {
            float p0 = __expf(s[nt][0] - mn0);
            float p1 = __expf(s[nt][1] - mn0);
            float p2 = __expf(s[nt][2] - mn1);
            float p3 = __expf(s[nt][3] - mn1);
            sum0 += p0 + p1; sum1 += p2 + p3;
            Ph[(r0 + gid) * AST + 8 * nt + 2 * tig]     = f2tf(p0);
            Ph[(r0 + gid) * AST + 8 * nt + 2 * tig + 1] = f2tf(p1);
            Ph[(r0 + gid + 8) * AST + 8 * nt + 2 * tig]     = f2tf(p2);
            Ph[(r0 + gid + 8) * AST + 8 * nt + 2 * tig + 1] = f2tf(p3);
        }
#pragma unroll
        for (int off = 1; off <= 2; off <<= 1) {
            sum0 += __shfl_xor_sync(0xffffffffu, sum0, off);
            sum1 += __shfl_xor_sync(0xffffffffu, sum1, off);
        }
        l0 = l0 * alpha0 + sum0;
        l1 = l1 * alpha1 + sum1;
        m0 = mn0; m1 = mn1;
#pragma unroll
        for (int nt = 0; nt < 8; nt++) {
            o[nt][0] *= alpha0; o[nt][1] *= alpha0;
            o[nt][2] *= alpha1; o[nt][3] *= alpha1;
        }
        __syncwarp();

#pragma unroll
        for (int kk = 0; kk < 64; kk += 8) {
            unsigned a[4];
            a[0] = Ph[(r0 + gid) * AST + kk + tig];
            a[1] = Ph[(r0 + gid + 8) * AST + kk + tig];
            a[2] = Ph[(r0 + gid) * AST + kk + tig + 4];
            a[3] = Ph[(r0 + gid + 8) * AST + kk + tig + 4];
#pragma unroll
            for (int nt = 0; nt < 8; nt++) {
                unsigned b0 = Vt[(8 * nt + gid) * AST + kk + tig];
                unsigned b1 = Vt[(8 * nt + gid) * AST + kk + tig + 4];
                mma_tf32(o[nt], a, b0, b1);
            }
        }
        __syncthreads();
    }

    float inv0 = 1.f / l0, inv1 = 1.f / l1;
    int row0 = qt * 128 + r0 + gid;
    int row1 = row0 + 8;
    float* O0 = Og + ((size_t)(b * Ss + row0)) * Cc + h * HD;
    float* O1 = Og + ((size_t)(b * Ss + row1)) * Cc + h * HD;
#pragma unroll
    for (int nt = 0; nt < 8; nt++) {
        *(float2*)(O0 + 8 * nt + 2 * tig) = make_float2(o[nt][0] * inv0, o[nt][1] * inv0);
        *(float2*)(O1 + 8 * nt + 2 * tig) = make_float2(o[nt][2] * inv1, o[nt][3] * inv1);
    }
}

// =====================================================================
extern "C" void kernel_launch(void* const* d_in, const int* in_sizes, int n_in,
                              void* d_out, int out_size)
{
    const float* x    = (const float*)d_in[0];
    const float* rope = (const float*)d_in[1];
    const float* wqkv = (const float*)d_in[2];
    const float* wout = (const float*)d_in[3];
    const float* qg   = (const float*)d_in[4];
    const float* qb   = (const float*)d_in[5];
    const float* kg   = (const float*)d_in[6];
    const float* kb   = (const float*)d_in[7];
    float* out = (float*)d_out;

    float *qkv, *q, *k, *v, *attn;
    cudaGetSymbolAddress((void**)&qkv,  g_qkv);
    cudaGetSymbolAddress((void**)&q,    g_q);
    cudaGetSymbolAddress((void**)&k,    g_k);
    cudaGetSymbolAddress((void**)&v,    g_v);
    cudaGetSymbolAddress((void**)&attn, g_attn);

    cudaFuncSetAttribute(gemm_3xtf32_kernel, cudaFuncAttributeMaxDynamicSharedMemorySize, GEMM_SMEM);
    cudaFuncSetAttribute(attn_tc_kernel, cudaFuncAttributeMaxDynamicSharedMemorySize, ATTN_SMEM);

    // 1) QKV projection (3xTF32, cp.async double-buffered)
    gemm_3xtf32_kernel<<<dim3(C3 / 128, BSs / 128), 256, GEMM_SMEM>>>(x, wqkv, qkv, BSs, C3, Cc);

    // 2) per-head LN + rotary + V copy -> [B,H,S,hd]
    lnrope_kernel<<<(Bb * Ss * Hh * 32) / 256, 256>>>(qkv, rope, qg, qb, kg, kb, q, k, v);

    // 3) attention (tensor-core flash)
    attn_tc_kernel<<<dim3(Ss / 128, Bb * Hh), 256, ATTN_SMEM>>>(q, k, v, attn);

    // 4) output projection (3xTF32)
    gemm_3xtf32_kernel<<<dim3(Cc / 128, BSs / 128), 256, GEMM_SMEM>>>(attn, wout, out, BSs, Cc, Cc);
}

// round 7
// speedup vs baseline: 2.5566x; 1.2857x over previous
#include <cuda_runtime.h>
#include <cuda_bf16.h>
#include <math.h>

// Problem dims (fixed for this problem instance)
#define Bb 2
#define Ss 2048
#define Cc 2048
#define HD 64
#define Hh 32              // Cc / HD
#define BSs (Bb * Ss)      // 4096
#define C3 (3 * Cc)        // 6144

// ---------------- scratch (no allocations allowed) ----------------
__device__ float g_qkv[(size_t)BSs * C3];        // [B,S,3C]
__device__ float g_q[(size_t)Bb * Hh * Ss * HD]; // [B,H,S,hd] (Q pre-scaled by 1/8)
__device__ float g_k[(size_t)Bb * Hh * Ss * HD];
__device__ float g_v[(size_t)Bb * Hh * Ss * HD];
__device__ float g_attn[(size_t)BSs * Cc];       // [B,S,C]
// bf16 hi/lo split operands for the projection GEMMs
__device__ __nv_bfloat16 g_xh[(size_t)BSs * Cc],  g_xl[(size_t)BSs * Cc];
__device__ __nv_bfloat16 g_wqh[(size_t)C3 * Cc],  g_wql[(size_t)C3 * Cc];
__device__ __nv_bfloat16 g_woh[(size_t)Cc * Cc],  g_wol[(size_t)Cc * Cc];
__device__ __nv_bfloat16 g_ah[(size_t)BSs * Cc],  g_al[(size_t)BSs * Cc];

// ---------------- tf32 helpers (attention kernel) ----------------
__device__ __forceinline__ unsigned f2tf(float f) {
    unsigned u;
    asm("cvt.rna.tf32.f32 %0, %1;" : "=r"(u) : "f"(f));
    return u;
}
__device__ __forceinline__ void split_tf(float x, unsigned& hi, unsigned& lo) {
    hi = f2tf(x);
    lo = f2tf(x - __uint_as_float(hi));
}
__device__ __forceinline__ void mma_tf32(float c[4], const unsigned a[4],
                                         unsigned b0, unsigned b1) {
    asm volatile(
        "mma.sync.aligned.m16n8k8.row.col.f32.tf32.tf32.f32 "
        "{%0,%1,%2,%3}, {%4,%5,%6,%7}, {%8,%9}, {%0,%1,%2,%3};\n"
        : "+f"(c[0]), "+f"(c[1]), "+f"(c[2]), "+f"(c[3])
        : "r"(a[0]), "r"(a[1]), "r"(a[2]), "r"(a[3]), "r"(b0), "r"(b1));
}
__device__ __forceinline__ void mma_bf16(float c[4], const unsigned a[4],
                                         unsigned b0, unsigned b1) {
    asm volatile(
        "mma.sync.aligned.m16n8k16.row.col.f32.bf16.bf16.f32 "
        "{%0,%1,%2,%3}, {%4,%5,%6,%7}, {%8,%9}, {%0,%1,%2,%3};\n"
        : "+f"(c[0]), "+f"(c[1]), "+f"(c[2]), "+f"(c[3])
        : "r"(a[0]), "r"(a[1]), "r"(a[2]), "r"(a[3]), "r"(b0), "r"(b1));
}

// ---------------- cp.async helpers ----------------
__device__ __forceinline__ void cp_async16(void* smem_dst, const void* gsrc) {
    unsigned sa = (unsigned)__cvta_generic_to_shared(smem_dst);
    asm volatile("cp.async.ca.shared.global [%0], [%1], 16;\n"
                 :: "r"(sa), "l"(gsrc) : "memory");
}
__device__ __forceinline__ void cp_commit() {
    asm volatile("cp.async.commit_group;\n" ::: "memory");
}
template <int N>
__device__ __forceinline__ void cp_wait_group() {
    asm volatile("cp.async.wait_group %0;\n" :: "n"(N) : "memory");
}

// =====================================================================
// fp32 -> (bf16 hi, bf16 lo) split pre-pass. 4 elements/thread.
// =====================================================================
__global__ __launch_bounds__(256) void split_bf16_kernel(
    const float4* __restrict__ in,
    __nv_bfloat162* __restrict__ hi, __nv_bfloat162* __restrict__ lo, int n4)
{
    int i = blockIdx.x * blockDim.x + threadIdx.x;
    if (i >= n4) return;
    float4 v = in[i];
    __nv_bfloat16 hx = __float2bfloat16_rn(v.x);
    __nv_bfloat16 hy = __float2bfloat16_rn(v.y);
    __nv_bfloat16 hz = __float2bfloat16_rn(v.z);
    __nv_bfloat16 hw = __float2bfloat16_rn(v.w);
    __nv_bfloat16 lx = __float2bfloat16_rn(v.x - __bfloat162float(hx));
    __nv_bfloat16 ly = __float2bfloat16_rn(v.y - __bfloat162float(hy));
    __nv_bfloat16 lz = __float2bfloat16_rn(v.z - __bfloat162float(hz));
    __nv_bfloat16 lw = __float2bfloat16_rn(v.w - __bfloat162float(hw));
    hi[2 * i]     = __nv_bfloat162(hx, hy);
    hi[2 * i + 1] = __nv_bfloat162(hz, hw);
    lo[2 * i]     = __nv_bfloat162(lx, ly);
    lo[2 * i + 1] = __nv_bfloat162(lz, lw);
}

// =====================================================================
// 3xBF16 tensor-core GEMM (NT): C[m,n] = sum_k A[m,k] * W[n,k]
// C += Ah*Bh + Al*Bh + Ah*Bl with pre-split bf16 hi/lo operand arrays.
// mma.sync.m16n8k16.bf16. 128x128 CTA tile, BK=32, 2-stage cp.async.
// Smem row = 32 k-elems packed as 16 words, stride 20 (conflict-free).
// =====================================================================
#define BST 20
#define BSTAGE (4 * 128 * BST)            // words per stage (Ah,Al,Bh,Bl)
#define GEMM_SMEM (2 * BSTAGE * 4)        // 80 KB

__global__ __launch_bounds__(256, 2) void gemm_3xbf16_kernel(
    const __nv_bfloat16* __restrict__ Ah, const __nv_bfloat16* __restrict__ Al,
    const __nv_bfloat16* __restrict__ Bh, const __nv_bfloat16* __restrict__ Bl,
    float* __restrict__ Cmat, int M, int N, int K)
{
    extern __shared__ unsigned bsm[];

    const int tid  = threadIdx.x;
    const int m0   = blockIdx.y * 128;
    const int n0   = blockIdx.x * 128;
    const int warp = tid >> 5;
    const int lane = tid & 31;
    const int gid  = lane >> 2;
    const int tig  = lane & 3;
    const int wm   = (warp & 1) * 64;
    const int wn   = (warp >> 1) * 32;

    // loader mapping: thread -> (row 0..127, half-row 0/1)
    const int lrow = tid >> 1;
    const int lhw  = (tid & 1) * 8;    // word offset within row
    const int lke  = (tid & 1) * 16;   // element offset within row

    float c[4][4][4];
#pragma unroll
    for (int mt = 0; mt < 4; mt++)
#pragma unroll
        for (int nt = 0; nt < 4; nt++)
#pragma unroll
            for (int i = 0; i < 4; i++) c[mt][nt][i] = 0.f;

    const __nv_bfloat16* Agh = Ah + (size_t)(m0 + lrow) * K + lke;
    const __nv_bfloat16* Agl = Al + (size_t)(m0 + lrow) * K + lke;
    const __nv_bfloat16* Bgh = Bh + (size_t)(n0 + lrow) * K + lke;
    const __nv_bfloat16* Bgl = Bl + (size_t)(n0 + lrow) * K + lke;

    const int ntiles = K >> 5;

    // stage loader: 8 cp.async16 per thread
    auto stage_load = [&](int stage, int t) {
        unsigned* S = bsm + stage * BSTAGE;
        const __nv_bfloat16* pa = Agh + t * 32;
        const __nv_bfloat16* pl = Agl + t * 32;
        const __nv_bfloat16* pb = Bgh + t * 32;
        const __nv_bfloat16* pc = Bgl + t * 32;
        unsigned base = lrow * BST + lhw;
        cp_async16(&S[base],                    pa);
        cp_async16(&S[base + 4],                pa + 8);
        cp_async16(&S[128 * BST + base],        pl);
        cp_async16(&S[128 * BST + base + 4],    pl + 8);
        cp_async16(&S[2 * 128 * BST + base],    pb);
        cp_async16(&S[2 * 128 * BST + base + 4], pb + 8);
        cp_async16(&S[3 * 128 * BST + base],    pc);
        cp_async16(&S[3 * 128 * BST + base + 4], pc + 8);
    };

    stage_load(0, 0);
    cp_commit();

    for (int t = 0; t < ntiles; t++) {
        const int st = t & 1;
        if (t + 1 < ntiles) {
            stage_load(st ^ 1, t + 1);
            cp_commit();
            cp_wait_group<1>();
        } else {
            cp_wait_group<0>();
        }
        __syncthreads();

        const unsigned* SA_H = bsm + st * BSTAGE;
        const unsigned* SA_L = SA_H + 128 * BST;
        const unsigned* SB_H = SA_H + 2 * 128 * BST;
        const unsigned* SB_L = SA_H + 3 * 128 * BST;

#pragma unroll
        for (int s2 = 0; s2 < 2; s2++) {       // two k16 steps per 32-k tile
            const int kw = s2 * 8 + tig;
            unsigned bh[4][2], bl[4][2];
#pragma unroll
            for (int nt = 0; nt < 4; nt++) {
                int col = wn + nt * 8 + gid;
                bh[nt][0] = SB_H[col * BST + kw];
                bh[nt][1] = SB_H[col * BST + kw + 4];
                bl[nt][0] = SB_L[col * BST + kw];
                bl[nt][1] = SB_L[col * BST + kw + 4];
            }
#pragma unroll
            for (int mt = 0; mt < 4; mt++) {
                int r0 = (wm + mt * 16 + gid) * BST;
                int r1 = r0 + 8 * BST;
                unsigned ah[4], al[4];
                ah[0] = SA_H[r0 + kw];     ah[1] = SA_H[r1 + kw];
                ah[2] = SA_H[r0 + kw + 4]; ah[3] = SA_H[r1 + kw + 4];
                al[0] = SA_L[r0 + kw];     al[1] = SA_L[r1 + kw];
                al[2] = SA_L[r0 + kw + 4]; al[3] = SA_L[r1 + kw + 4];
#pragma unroll
                for (int nt = 0; nt < 4; nt++) {
                    mma_bf16(c[mt][nt], ah, bh[nt][0], bh[nt][1]);
                    mma_bf16(c[mt][nt], al, bh[nt][0], bh[nt][1]);
                    mma_bf16(c[mt][nt], ah, bl[nt][0], bl[nt][1]);
                }
            }
        }
        __syncthreads();
    }

#pragma unroll
    for (int mt = 0; mt < 4; mt++) {
        int row0 = m0 + wm + mt * 16 + gid;
        int row1 = row0 + 8;
#pragma unroll
        for (int nt = 0; nt < 4; nt++) {
            int col = n0 + wn + nt * 8 + tig * 2;
            *(float2*)(Cmat + (size_t)row0 * N + col) = make_float2(c[mt][nt][0], c[mt][nt][1]);
            *(float2*)(Cmat + (size_t)row1 * N + col) = make_float2(c[mt][nt][2], c[mt][nt][3]);
        }
    }
}

// =====================================================================
// Fused LayerNorm (per-head) + rotary + V copy. One warp per (b,s,h).
// Q pre-scaled by 1/8. Output layout: [B,H,S,hd].
// =====================================================================
__global__ __launch_bounds__(256) void lnrope_kernel(
    const float* __restrict__ qkv, const float* __restrict__ rope,
    const float* __restrict__ qg, const float* __restrict__ qb,
    const float* __restrict__ kg, const float* __restrict__ kb,
    float* __restrict__ Qo, float* __restrict__ Ko, float* __restrict__ Vo)
{
    int gw   = (blockIdx.x * blockDim.x + threadIdx.x) >> 5;
    int lane = threadIdx.x & 31;
    if (gw >= Bb * Ss * Hh) return;
    int h = gw % Hh;
    int s = (gw / Hh) % Ss;
    int b = gw / (Hh * Ss);

    const float* base = qkv + ((size_t)(b * Ss + s)) * C3 + h * (3 * HD);
    float4 r4 = *(const float4*)(rope + (size_t)s * 128 + lane * 4);
    size_t obase = (((size_t)(b * Hh + h)) * Ss + s) * HD + 2 * lane;

    float gq0 = qg[2 * lane], gq1 = qg[2 * lane + 1];
    float bq0 = qb[2 * lane], bq1 = qb[2 * lane + 1];
    float gk0 = kg[2 * lane], gk1 = kg[2 * lane + 1];
    float bk0 = kb[2 * lane], bk1 = kb[2 * lane + 1];

    {
        float2 x2 = *(const float2*)(base + 2 * lane);
        float sum = x2.x + x2.y;
#pragma unroll
        for (int o = 16; o; o >>= 1) sum += __shfl_xor_sync(0xffffffffu, sum, o);
        float mean = sum * (1.f / 64.f);
        float d0 = x2.x - mean, d1 = x2.y - mean;
        float vs = d0 * d0 + d1 * d1;
#pragma unroll
        for (int o = 16; o; o >>= 1) vs += __shfl_xor_sync(0xffffffffu, vs, o);
        float inv = rsqrtf(vs * (1.f / 64.f) + 1e-5f);
        float n0 = d0 * inv * gq0 + bq0;
        float n1 = d1 * inv * gq1 + bq1;
        float o0 = r4.x * n0 + r4.y * n1;
        float o1 = r4.z * n0 + r4.w * n1;
        *(float2*)(Qo + obase) = make_float2(o0 * 0.125f, o1 * 0.125f);
    }
    {
        float2 x2 = *(const float2*)(base + HD + 2 * lane);
        float sum = x2.x + x2.y;
#pragma unroll
        for (int o = 16; o; o >>= 1) sum += __shfl_xor_sync(0xffffffffu, sum, o);
        float mean = sum * (1.f / 64.f);
        float d0 = x2.x - mean, d1 = x2.y - mean;
        float vs = d0 * d0 + d1 * d1;
#pragma unroll
        for (int o = 16; o; o >>= 1) vs += __shfl_xor_sync(0xffffffffu, vs, o);
        float inv = rsqrtf(vs * (1.f / 64.f) + 1e-5f);
        float n0 = d0 * inv * gk0 + bk0;
        float n1 = d1 * inv * gk1 + bk1;
        float o0 = r4.x * n0 + r4.y * n1;
        float o1 = r4.z * n0 + r4.w * n1;
        *(float2*)(Ko + obase) = make_float2(o0, o1);
    }
    {
        float2 x2 = *(const float2*)(base + 2 * HD + 2 * lane);
        *(float2*)(Vo + obase) = x2;
    }
}

// =====================================================================
// Tensor-core flash attention (tf32). Unchanged from R4/R5.
// =====================================================================
#define AST 68
#define OFF_QH 0
#define OFF_QL (128 * AST)
#define OFF_KH (2 * 128 * AST)
#define OFF_KL (OFF_KH + 64 * AST)
#define OFF_VT (OFF_KL + 64 * AST)
#define OFF_PH (OFF_VT + 64 * AST)
#define ATTN_WORDS (OFF_PH + 128 * AST)
#define ATTN_SMEM (ATTN_WORDS * 4)

__global__ __launch_bounds__(256) void attn_tc_kernel(
    const float* __restrict__ Qg, const float* __restrict__ Kg,
    const float* __restrict__ Vg, float* __restrict__ Og)
{
    extern __shared__ unsigned asm_[];
    unsigned* Qh = asm_ + OFF_QH;
    unsigned* Ql = asm_ + OFF_QL;
    unsigned* Kh = asm_ + OFF_KH;
    unsigned* Kl = asm_ + OFF_KL;
    unsigned* Vt = asm_ + OFF_VT;   // V^T: [d][kv]
    unsigned* Ph = asm_ + OFF_PH;

    const int bh = blockIdx.y;
    const int b  = bh >> 5;
    const int h  = bh & (Hh - 1);
    const int qt = blockIdx.x;

    const float* Q = Qg + ((size_t)bh * Ss + qt * 128) * HD;
    const float* K = Kg + (size_t)bh * Ss * HD;
    const float* V = Vg + (size_t)bh * Ss * HD;

    const int tid  = threadIdx.x;
    const int warp = tid >> 5, lane = tid & 31;
    const int gid  = lane >> 2, tig = lane & 3;
    const int r0   = warp * 16;

#pragma unroll
    for (int j = 0; j < 8; j++) {
        int lin = tid + j * 256;
        int row = lin & 127;
        int c4  = (lin >> 7) << 2;
        float4 v = *(const float4*)(Q + (size_t)row * HD + c4);
        unsigned hx, lx;
        split_tf(v.x, hx, lx); Qh[row * AST + c4 + 0] = hx; Ql[row * AST + c4 + 0] = lx;
        split_tf(v.y, hx, lx); Qh[row * AST + c4 + 1] = hx; Ql[row * AST + c4 + 1] = lx;
        split_tf(v.z, hx, lx); Qh[row * AST + c4 + 2] = hx; Ql[row * AST + c4 + 2] = lx;
        split_tf(v.w, hx, lx); Qh[row * AST + c4 + 3] = hx; Ql[row * AST + c4 + 3] = lx;
    }

    float o[8][4];
#pragma unroll
    for (int nt = 0; nt < 8; nt++)
#pragma unroll
        for (int i = 0; i < 4; i++) o[nt][i] = 0.f;
    float m0 = -1e30f, m1 = -1e30f, l0 = 0.f, l1 = 0.f;

    for (int kt = 0; kt < Ss / 64; kt++) {
        const float* Kt = K + (size_t)kt * 64 * HD;
        const float* Vtile = V + (size_t)kt * 64 * HD;

#pragma unroll
        for (int j = 0; j < 4; j++) {
            int lin = tid + j * 256;
            int row = lin & 63;
            int c4  = (lin >> 6) << 2;
            float4 v = *(const float4*)(Kt + (size_t)row * HD + c4);
            unsigned hx, lx;
            split_tf(v.x, hx, lx); Kh[row * AST + c4 + 0] = hx; Kl[row * AST + c4 + 0] = lx;
            split_tf(v.y, hx, lx); Kh[row * AST + c4 + 1] = hx; Kl[row * AST + c4 + 1] = lx;
            split_tf(v.z, hx, lx); Kh[row * AST + c4 + 2] = hx; Kl[row * AST + c4 + 2] = lx;
            split_tf(v.w, hx, lx); Kh[row * AST + c4 + 3] = hx; Kl[row * AST + c4 + 3] = lx;
        }
#pragma unroll
        for (int j = 0; j < 4; j++) {
            int row = warp * 8 + (lane & 7);
            int c4  = j * 16 + ((lane >> 3) << 2);
            float4 v = *(const float4*)(Vtile + (size_t)row * HD + c4);
            Vt[(c4 + 0) * AST + row] = f2tf(v.x);
            Vt[(c4 + 1) * AST + row] = f2tf(v.y);
            Vt[(c4 + 2) * AST + row] = f2tf(v.z);
            Vt[(c4 + 3) * AST + row] = f2tf(v.w);
        }
        __syncthreads();

        float s[8][4];
#pragma unroll
        for (int nt = 0; nt < 8; nt++)
#pragma unroll
            for (int i = 0; i < 4; i++) s[nt][i] = 0.f;

#pragma unroll
        for (int kk = 0; kk < 64; kk += 8) {
            unsigned ah[4], al[4];
            ah[0] = Qh[(r0 + gid) * AST + kk + tig];
            ah[1] = Qh[(r0 + gid + 8) * AST + kk + tig];
            ah[2] = Qh[(r0 + gid) * AST + kk + tig + 4];
            ah[3] = Qh[(r0 + gid + 8) * AST + kk + tig + 4];
            al[0] = Ql[(r0 + gid) * AST + kk + tig];
            al[1] = Ql[(r0 + gid + 8) * AST + kk + tig];
            al[2] = Ql[(r0 + gid) * AST + kk + tig + 4];
            al[3] = Ql[(r0 + gid + 8) * AST + kk + tig + 4];
#pragma unroll
            for (int nt = 0; nt < 8; nt++) {
                unsigned bh0 = Kh[(8 * nt + gid) * AST + kk + tig];
                unsigned bh1 = Kh[(8 * nt + gid) * AST + kk + tig + 4];
                unsigned bl0 = Kl[(8 * nt + gid) * AST + kk + tig];
                unsigned bl1 = Kl[(8 * nt + gid) * AST + kk + tig + 4];
                mma_tf32(s[nt], ah, bh0, bh1);
                mma_tf32(s[nt], al, bh0, bh1);
                mma_tf32(s[nt], ah, bl0, bl1);
            }
        }

        float rmax0 = -1e30f, rmax1 = -1e30f;
#pragma unroll
        for (int nt = 0; nt < 8; nt++) {
            rmax0 = fmaxf(rmax0, fmaxf(s[nt][0], s[nt][1]));
            rmax1 = fmaxf(rmax1, fmaxf(s[nt][2], s[nt][3]));
        }
#pragma unroll
        for (int off = 1; off <= 2; off <<= 1) {
            rmax0 = fmaxf(rmax0, __shfl_xor_sync(0xffffffffu, rmax0, off));
            rmax1 = fmaxf(rmax1, __shfl_xor_sync(0xffffffffu, rmax1, off));
        }
        float mn0 = fmaxf(m0, rmax0), mn1 = fmaxf(m1, rmax1);
        float alpha0 = __expf(m0 - mn0), alpha1 = __expf(m1 - mn1);
        float sum0 = 0.f, sum1 = 0.f;
#pragma unroll
        for (int nt = 0; nt < 8; nt++) {
            float p0 = __expf(s[nt][0] - mn0);
            float p1 = __expf(s[nt][1] - mn0);
            float p2 = __expf(s[nt][2] - mn1);
            float p3 = __expf(s[nt][3] - mn1);
            sum0 += p0 + p1; sum1 += p2 + p3;
            Ph[(r0 + gid) * AST + 8 * nt + 2 * tig]     = f2tf(p0);
            Ph[(r0 + gid) * AST + 8 * nt + 2 * tig + 1] = f2tf(p1);
            Ph[(r0 + gid + 8) * AST + 8 * nt + 2 * tig]     = f2tf(p2);
            Ph[(r0 + gid + 8) * AST + 8 * nt + 2 * tig + 1] = f2tf(p3);
        }
#pragma unroll
        for (int off = 1; off <= 2; off <<= 1) {
            sum0 += __shfl_xor_sync(0xffffffffu, sum0, off);
            sum1 += __shfl_xor_sync(0xffffffffu, sum1, off);
        }
        l0 = l0 * alpha0 + sum0;
        l1 = l1 * alpha1 + sum1;
        m0 = mn0; m1 = mn1;
#pragma unroll
        for (int nt = 0; nt < 8; nt++) {
            o[nt][0] *= alpha0; o[nt][1] *= alpha0;
            o[nt][2] *= alpha1; o[nt][3] *= alpha1;
        }
        __syncwarp();

#pragma unroll
        for (int kk = 0; kk < 64; kk += 8) {
            unsigned a[4];
            a[0] = Ph[(r0 + gid) * AST + kk + tig];
            a[1] = Ph[(r0 + gid + 8) * AST + kk + tig];
            a[2] = Ph[(r0 + gid) * AST + kk + tig + 4];
            a[3] = Ph[(r0 + gid + 8) * AST + kk + tig + 4];
#pragma unroll
            for (int nt = 0; nt < 8; nt++) {
                unsigned b0 = Vt[(8 * nt + gid) * AST + kk + tig];
                unsigned b1 = Vt[(8 * nt + gid) * AST + kk + tig + 4];
                mma_tf32(o[nt], a, b0, b1);
            }
        }
        __syncthreads();
    }

    float inv0 = 1.f / l0, inv1 = 1.f / l1;
    int row0 = qt * 128 + r0 + gid;
    int row1 = row0 + 8;
    float* O0 = Og + ((size_t)(b * Ss + row0)) * Cc + h * HD;
    float* O1 = Og + ((size_t)(b * Ss + row1)) * Cc + h * HD;
#pragma unroll
    for (int nt = 0; nt < 8; nt++) {
        *(float2*)(O0 + 8 * nt + 2 * tig) = make_float2(o[nt][0] * inv0, o[nt][1] * inv0);
        *(float2*)(O1 + 8 * nt + 2 * tig) = make_float2(o[nt][2] * inv1, o[nt][3] * inv1);
    }
}

// =====================================================================
extern "C" void kernel_launch(void* const* d_in, const int* in_sizes, int n_in,
                              void* d_out, int out_size)
{
    const float* x    = (const float*)d_in[0];
    const float* rope = (const float*)d_in[1];
    const float* wqkv = (const float*)d_in[2];
    const float* wout = (const float*)d_in[3];
    const float* qg   = (const float*)d_in[4];
    const float* qb   = (const float*)d_in[5];
    const float* kg   = (const float*)d_in[6];
    const float* kb   = (const float*)d_in[7];
    float* out = (float*)d_out;

    float *qkv, *q, *k, *v, *attn;
    __nv_bfloat16 *xh, *xl, *wqh, *wql, *woh, *wol, *ah, *al;
    cudaGetSymbolAddress((void**)&qkv,  g_qkv);
    cudaGetSymbolAddress((void**)&q,    g_q);
    cudaGetSymbolAddress((void**)&k,    g_k);
    cudaGetSymbolAddress((void**)&v,    g_v);
    cudaGetSymbolAddress((void**)&attn, g_attn);
    cudaGetSymbolAddress((void**)&xh,   g_xh);
    cudaGetSymbolAddress((void**)&xl,   g_xl);
    cudaGetSymbolAddress((void**)&wqh,  g_wqh);
    cudaGetSymbolAddress((void**)&wql,  g_wql);
    cudaGetSymbolAddress((void**)&woh,  g_woh);
    cudaGetSymbolAddress((void**)&wol,  g_wol);
    cudaGetSymbolAddress((void**)&ah,   g_ah);
    cudaGetSymbolAddress((void**)&al,   g_al);

    cudaFuncSetAttribute(gemm_3xbf16_kernel, cudaFuncAttributeMaxDynamicSharedMemorySize, GEMM_SMEM);
    cudaFuncSetAttribute(attn_tc_kernel, cudaFuncAttributeMaxDynamicSharedMemorySize, ATTN_SMEM);

    // 0) hi/lo bf16 splits of GEMM inputs
    {
        int n4 = (BSs * Cc) / 4;
        split_bf16_kernel<<<(n4 + 255) / 256, 256>>>((const float4*)x,
            (__nv_bfloat162*)xh, (__nv_bfloat162*)xl, n4);
        int w4 = (C3 * Cc) / 4;
        split_bf16_kernel<<<(w4 + 255) / 256, 256>>>((const float4*)wqkv,
            (__nv_bfloat162*)wqh, (__nv_bfloat162*)wql, w4);
        int o4 = (Cc * Cc) / 4;
        split_bf16_kernel<<<(o4 + 255) / 256, 256>>>((const float4*)wout,
            (__nv_bfloat162*)woh, (__nv_bfloat162*)wol, o4);
    }

    // 1) QKV projection (3xBF16)
    gemm_3xbf16_kernel<<<dim3(C3 / 128, BSs / 128), 256, GEMM_SMEM>>>(
        xh, xl, wqh, wql, qkv, BSs, C3, Cc);

    // 2) per-head LN + rotary + V copy -> [B,H,S,hd]
    lnrope_kernel<<<(Bb * Ss * Hh * 32) / 256, 256>>>(qkv, rope, qg, qb, kg, kb, q, k, v);

    // 3) attention (tensor-core flash, tf32)
    attn_tc_kernel<<<dim3(Ss / 128, Bb * Hh), 256, ATTN_SMEM>>>(q, k, v, attn);

    // 4) split attention output, then output projection (3xBF16)
    {
        int n4 = (BSs * Cc) / 4;
        split_bf16_kernel<<<(n4 + 255) / 256, 256>>>((const float4*)attn,
            (__nv_bfloat162*)ah, (__nv_bfloat162*)al, n4);
    }
    gemm_3xbf16_kernel<<<dim3(Cc / 128, BSs / 128), 256, GEMM_SMEM>>>(
        ah, al, woh, wol, out, BSs, Cc, Cc);
}